// round 15
// baseline (speedup 1.0000x reference)
#include <cuda_runtime.h>
#include <cuda_bf16.h>
#include <math.h>
#include <stdint.h>

#define NN 50000
#define NE 800000
#define D  128

// ---------------- scratch ----------------
static __device__ float g_Q  [NN * D];
static __device__ float g_Kb [NN * D];
static __device__ float g_V  [NN * D];
static __device__ float g_wV [NN * D];
static __device__ float g_z  [NN * 8];
static __device__ float g_h2 [NN * D];
static __device__ float g_e2 [(size_t)NE * D];
static __device__ float g_stats[4 * 2 * D];
static __device__ float g_bnab [4 * 2 * D];
static __device__ __nv_bfloat16 g_wimg[458752];

// ---------------- merged weight prep ----------------
struct PrepArgs { const float* src[10]; };

__global__ void prep_all(PrepArgs args, __nv_bfloat16* __restrict__ img)
{
    int idx = blockIdx.x * blockDim.x + threadIdx.x;
    if (idx >= 229376) return;
    int w, off, K, N;
    size_t ooff;
    if (idx < 98304) {
        w = idx >> 14; off = idx & 16383; K = 128; N = 128;
        ooff = (size_t)w * 32768;
    } else {
        int t = idx - 98304;
        w = 6 + (t >> 15); off = t & 32767;
        if (w < 8) { K = 128; N = 256; } else { K = 256; N = 128; }
        ooff = 196608 + (size_t)(w - 6) * 65536;
    }
    const float* W = args.src[w];
    int k = off / N, n = off - k * N;
    float wv = __ldg(W + off);
    __nv_bfloat16 hi = __float2bfloat16(wv);
    __nv_bfloat16 lo = __float2bfloat16(wv - __bfloat162float(hi));
    int kstep = k >> 4, kin = k & 15;
    int reg  = (kin >> 3) & 1;
    int tid4 = (kin >> 1) & 3;
    int p    = kin & 1;
    int gg   = n & 7;
    int ntile = n >> 3;
    int lane = gg * 4 + tid4;
    size_t idx4 = ((size_t)kstep * (N >> 3) + ntile) * 32 + lane;
    img[ooff + idx4 * 8 + reg * 2 + p]     = hi;
    img[ooff + idx4 * 8 + 4 + reg * 2 + p] = lo;
}

__device__ __forceinline__ void mma16816(float* c, const uint32_t* a, uint32_t b0, uint32_t b1)
{
    asm volatile(
        "mma.sync.aligned.m16n8k16.row.col.f32.bf16.bf16.f32 "
        "{%0,%1,%2,%3}, {%4,%5,%6,%7}, {%8,%9}, {%0,%1,%2,%3};"
        : "+f"(c[0]), "+f"(c[1]), "+f"(c[2]), "+f"(c[3])
        : "r"(a[0]), "r"(a[1]), "r"(a[2]), "r"(a[3]), "r"(b0), "r"(b1));
}

__device__ __forceinline__ void ldsm4(uint32_t r[4], uint32_t addr)
{
    asm volatile("ldmatrix.sync.aligned.m8n8.x4.shared.b16 {%0,%1,%2,%3}, [%4];"
                 : "=r"(r[0]), "=r"(r[1]), "=r"(r[2]), "=r"(r[3]) : "r"(addr));
}

template<int STRIDE>
__device__ __forceinline__ uint32_t ldsm_off(int r0, int lane)
{
    int row = r0 + (lane & 7) + ((lane >> 3) & 1) * 8;
    int col = ((lane >> 4) & 1) * 8;
    return (uint32_t)((row * STRIDE + col) * 2);
}

template<int STRIDE>
__device__ __forceinline__ void load_afrag_ldsm(uint32_t shH, uint32_t shL, uint32_t aoff,
                                                uint32_t ksbyte, uint32_t ah[2][4], uint32_t al[2][4])
{
    ldsm4(ah[0], shH + aoff + ksbyte);
    ldsm4(ah[1], shH + aoff + ksbyte + 16 * STRIDE * 2);
    ldsm4(al[0], shL + aoff + ksbyte);
    ldsm4(al[1], shL + aoff + ksbyte + 16 * STRIDE * 2);
}

__device__ __forceinline__ void split_store(__nv_bfloat16* Ah, __nv_bfloat16* Al,
                                            int off, float4 v)
{
    __nv_bfloat162 h0 = __floats2bfloat162_rn(v.x, v.y);
    __nv_bfloat162 h1 = __floats2bfloat162_rn(v.z, v.w);
    __nv_bfloat162 l0 = __floats2bfloat162_rn(v.x - __bfloat162float(h0.x),
                                              v.y - __bfloat162float(h0.y));
    __nv_bfloat162 l1 = __floats2bfloat162_rn(v.z - __bfloat162float(h1.x),
                                              v.w - __bfloat162float(h1.y));
    *(__nv_bfloat162*)(Ah + off)     = h0;
    *(__nv_bfloat162*)(Ah + off + 2) = h1;
    *(__nv_bfloat162*)(Al + off)     = l0;
    *(__nv_bfloat162*)(Al + off + 2) = l1;
}

__device__ __forceinline__ void mma_pair(float acc0[2][4], float acc1[2][4],
                                         const uint32_t ah[2][4], const uint32_t al[2][4],
                                         uint4 b0, uint4 b1)
{
    mma16816(acc0[0], ah[0], b0.x, b0.y);
    mma16816(acc0[1], ah[1], b0.x, b0.y);
    mma16816(acc1[0], ah[0], b1.x, b1.y);
    mma16816(acc1[1], ah[1], b1.x, b1.y);
    mma16816(acc0[0], ah[0], b0.z, b0.w);
    mma16816(acc0[1], ah[1], b0.z, b0.w);
    mma16816(acc1[0], ah[0], b1.z, b1.w);
    mma16816(acc1[1], ah[1], b1.z, b1.w);
    mma16816(acc0[0], al[0], b0.x, b0.y);
    mma16816(acc0[1], al[1], b0.x, b0.y);
    mma16816(acc1[0], al[0], b1.x, b1.y);
    mma16816(acc1[1], al[1], b1.x, b1.y);
}

// ---------------- h-side O-proj GEMM, 64-row tiles, 3 CTA/SM ----------------
template<int BIAS, int RESM, int DO_STATS, int DIVZ>
__global__ void __launch_bounds__(256, 3)
mm_k(const float* __restrict__ X, const __nv_bfloat16* __restrict__ Wimg,
     const float* __restrict__ bias, const float* __restrict__ res,
     const float* __restrict__ res_ab,
     const float* __restrict__ zdiv, float* __restrict__ stats,
     float* __restrict__ C, int M)
{
    constexpr int SAP = 136;
    extern __shared__ __nv_bfloat16 sA[];
    __nv_bfloat16* Ah = sA;
    __nv_bfloat16* Al = sA + 64 * SAP;

    const int tid  = threadIdx.x;
    const int w    = tid >> 5, lane = tid & 31;
    const int wr   = w >> 2, wc = w & 3;
    const int g    = lane >> 2, tid4 = lane & 3;
    const int row0 = blockIdx.y * 64;

    const uint4* Bimg = (const uint4*)Wimg;

    float acc[4][2][4];
    #pragma unroll
    for (int nt = 0; nt < 4; nt++)
        #pragma unroll
        for (int mt = 0; mt < 2; mt++)
            #pragma unroll
            for (int i = 0; i < 4; i++) acc[nt][mt][i] = 0.f;

    #pragma unroll 2
    for (int i = tid; i < 2048; i += 256) {
        int r = i >> 5, c4 = i & 31, col = c4 * 4;
        float4 v = make_float4(0.f, 0.f, 0.f, 0.f);
        int gr = row0 + r;
        if (gr < M) {
            v = __ldg((const float4*)(X + (size_t)gr * 128) + c4);
            if (DIVZ) {
                float inv = 1.0f / (__ldg(zdiv + gr * 8 + (c4 >> 2)) + 1e-6f);
                v.x *= inv; v.y *= inv; v.z *= inv; v.w *= inv;
            }
        }
        split_store(Ah, Al, r * SAP + col, v);
    }
    __syncthreads();

    const uint32_t shAh = (uint32_t)__cvta_generic_to_shared(Ah);
    const uint32_t shAl = (uint32_t)__cvta_generic_to_shared(Al);
    const uint32_t aoff = ldsm_off<SAP>(wr * 32, lane);

    #pragma unroll
    for (int ks = 0; ks < 8; ks++) {
        uint32_t ah[2][4], al[2][4];
        load_afrag_ldsm<SAP>(shAh, shAl, aoff, ks * 32, ah, al);
        #pragma unroll
        for (int ntp = 0; ntp < 2; ntp++) {
            uint4 b0 = __ldg(Bimg + ((size_t)ks * 16 + (wc * 4 + ntp * 2 + 0)) * 32 + lane);
            uint4 b1 = __ldg(Bimg + ((size_t)ks * 16 + (wc * 4 + ntp * 2 + 1)) * 32 + lane);
            mma_pair(acc[ntp * 2], acc[ntp * 2 + 1], ah, al, b0, b1);
        }
    }

    float s1[8], s2[8];
    if (DO_STATS) {
        #pragma unroll
        for (int j = 0; j < 8; j++) { s1[j] = 0.f; s2[j] = 0.f; }
    }
    #pragma unroll
    for (int mt = 0; mt < 2; mt++)
        #pragma unroll
        for (int half = 0; half < 2; half++) {
            int gr = row0 + wr * 32 + mt * 16 + g + half * 8;
            if (gr >= M) continue;
            #pragma unroll
            for (int nt = 0; nt < 4; nt++) {
                int col = wc * 32 + nt * 8 + tid4 * 2;
                float o0 = acc[nt][mt][half * 2 + 0];
                float o1 = acc[nt][mt][half * 2 + 1];
                if (BIAS) { o0 += __ldg(bias + col); o1 += __ldg(bias + col + 1); }
                if (RESM) {
                    float2 rv = __ldg((const float2*)(res + (size_t)gr * D + col));
                    o0 += rv.x; o1 += rv.y;
                }
                if (DO_STATS) {
                    s1[nt * 2 + 0] += o0; s2[nt * 2 + 0] = fmaf(o0, o0, s2[nt * 2 + 0]);
                    s1[nt * 2 + 1] += o1; s2[nt * 2 + 1] = fmaf(o1, o1, s2[nt * 2 + 1]);
                }
                *(float2*)(C + (size_t)gr * D + col) = make_float2(o0, o1);
            }
        }
    if (DO_STATS) {
        #pragma unroll
        for (int j = 0; j < 8; j++) {
            float a = s1[j], q = s2[j];
            a += __shfl_xor_sync(0xffffffffu, a, 4);  q += __shfl_xor_sync(0xffffffffu, q, 4);
            a += __shfl_xor_sync(0xffffffffu, a, 8);  q += __shfl_xor_sync(0xffffffffu, q, 8);
            a += __shfl_xor_sync(0xffffffffu, a, 16); q += __shfl_xor_sync(0xffffffffu, q, 16);
            if (g == 0) {
                int col = wc * 32 + (j >> 1) * 8 + tid4 * 2 + (j & 1);
                atomicAdd(stats + col, a);
                atomicAdd(stats + 128 + col, q);
            }
        }
    }
}

// ---------------- fused QKV, 64-row tiles, 3 CTA/SM ----------------
__global__ void __launch_bounds__(256, 3)
qkv_k(const float* __restrict__ X,
      const __nv_bfloat16* __restrict__ Wq, const __nv_bfloat16* __restrict__ Wk,
      const __nv_bfloat16* __restrict__ Wv,
      float* __restrict__ Cq, float* __restrict__ Ck, float* __restrict__ Cv, int M)
{
    constexpr int SAP = 136;
    extern __shared__ __nv_bfloat16 sA[];
    __nv_bfloat16* Ah = sA;
    __nv_bfloat16* Al = sA + 64 * SAP;

    const int tid  = threadIdx.x;
    const int w    = tid >> 5, lane = tid & 31;
    const int wr   = w >> 2, wc = w & 3;
    const int g    = lane >> 2, tid4 = lane & 3;
    const int row0 = blockIdx.y * 64;

    #pragma unroll 2
    for (int i = tid; i < 2048; i += 256) {
        int r = i >> 5, c4 = i & 31, col = c4 * 4;
        float4 v = make_float4(0.f, 0.f, 0.f, 0.f);
        int gr = row0 + r;
        if (gr < M) v = __ldg((const float4*)(X + (size_t)gr * 128) + c4);
        split_store(Ah, Al, r * SAP + col, v);
    }
    __syncthreads();

    const uint32_t shAh = (uint32_t)__cvta_generic_to_shared(Ah);
    const uint32_t shAl = (uint32_t)__cvta_generic_to_shared(Al);
    const uint32_t aoff = ldsm_off<SAP>(wr * 32, lane);

    const __nv_bfloat16* Ws[3] = {Wq, Wk, Wv};
    float* Cs[3] = {Cq, Ck, Cv};
    #pragma unroll 1
    for (int wsel = 0; wsel < 3; wsel++) {
        const uint4* Bimg = (const uint4*)Ws[wsel];
        float* C = Cs[wsel];
        float acc[4][2][4];
        #pragma unroll
        for (int nt = 0; nt < 4; nt++)
            #pragma unroll
            for (int mt = 0; mt < 2; mt++)
                #pragma unroll
                for (int i = 0; i < 4; i++) acc[nt][mt][i] = 0.f;
        #pragma unroll
        for (int ks = 0; ks < 8; ks++) {
            uint32_t ah[2][4], al[2][4];
            load_afrag_ldsm<SAP>(shAh, shAl, aoff, ks * 32, ah, al);
            #pragma unroll
            for (int ntp = 0; ntp < 2; ntp++) {
                uint4 b0 = __ldg(Bimg + ((size_t)ks * 16 + (wc * 4 + ntp * 2 + 0)) * 32 + lane);
                uint4 b1 = __ldg(Bimg + ((size_t)ks * 16 + (wc * 4 + ntp * 2 + 1)) * 32 + lane);
                mma_pair(acc[ntp * 2], acc[ntp * 2 + 1], ah, al, b0, b1);
            }
        }
        #pragma unroll
        for (int mt = 0; mt < 2; mt++)
            #pragma unroll
            for (int half = 0; half < 2; half++) {
                int gr = row0 + wr * 32 + mt * 16 + g + half * 8;
                if (gr >= M) continue;
                #pragma unroll
                for (int nt = 0; nt < 4; nt++) {
                    int col = wc * 32 + nt * 8 + tid4 * 2;
                    *(float2*)(C + (size_t)gr * D + col) =
                        make_float2(acc[nt][mt][half * 2 + 0], acc[nt][mt][half * 2 + 1]);
                }
            }
    }
}

// ---------------- fused edge pipeline, 3 CTA/SM ----------------
__global__ void __launch_bounds__(256, 3)
epj_k(const float* __restrict__ X, const __nv_bfloat16* __restrict__ W1img,
      const __nv_bfloat16* __restrict__ W2img, const float* __restrict__ bias,
      const int* __restrict__ src, const int* __restrict__ dst,
      float* __restrict__ stats, float* __restrict__ C, int M)
{
    constexpr int SAP = 136;
    extern __shared__ __nv_bfloat16 sm[];
    __nv_bfloat16* Ah = sm;
    __nv_bfloat16* Al = sm + 64 * SAP;
    __nv_bfloat16* Sh = sm + 2 * 64 * SAP;
    __nv_bfloat16* Sl = sm + 3 * 64 * SAP;

    const int tid  = threadIdx.x;
    const int w    = tid >> 5, lane = tid & 31;
    const int wr   = w >> 2, wc = w & 3;
    const int g    = lane >> 2, tid4 = lane & 3;
    const int row0 = blockIdx.x * 64;

    const uint4* B1 = (const uint4*)W1img;
    const uint4* B2 = (const uint4*)W2img;

    #pragma unroll 2
    for (int i = tid; i < 2048; i += 256) {
        int r = i >> 5, c4 = i & 31, col = c4 * 4;
        float4 v = make_float4(0.f, 0.f, 0.f, 0.f);
        int gr = row0 + r;
        if (gr < M) v = __ldg((const float4*)(X + (size_t)gr * 128) + c4);
        split_store(Ah, Al, r * SAP + col, v);
    }
    __syncthreads();

    const uint32_t shAh = (uint32_t)__cvta_generic_to_shared(Ah);
    const uint32_t shAl = (uint32_t)__cvta_generic_to_shared(Al);
    const uint32_t shSh = (uint32_t)__cvta_generic_to_shared(Sh);
    const uint32_t shSl = (uint32_t)__cvta_generic_to_shared(Sl);
    const uint32_t aoff = ldsm_off<SAP>(wr * 32, lane);

    float acc1[4][2][4];
    #pragma unroll
    for (int nt = 0; nt < 4; nt++)
        #pragma unroll
        for (int mt = 0; mt < 2; mt++)
            #pragma unroll
            for (int i = 0; i < 4; i++) acc1[nt][mt][i] = 0.f;
    #pragma unroll
    for (int ks = 0; ks < 8; ks++) {
        uint32_t ah[2][4], al[2][4];
        load_afrag_ldsm<SAP>(shAh, shAl, aoff, ks * 32, ah, al);
        #pragma unroll
        for (int ntp = 0; ntp < 2; ntp++) {
            uint4 b0 = __ldg(B1 + ((size_t)ks * 16 + (wc * 4 + ntp * 2 + 0)) * 32 + lane);
            uint4 b1 = __ldg(B1 + ((size_t)ks * 16 + (wc * 4 + ntp * 2 + 1)) * 32 + lane);
            mma_pair(acc1[ntp * 2], acc1[ntp * 2 + 1], ah, al, b0, b1);
        }
    }
    #pragma unroll
    for (int mt = 0; mt < 2; mt++)
        #pragma unroll
        for (int half = 0; half < 2; half++) {
            int rl = wr * 32 + mt * 16 + g + half * 8;
            #pragma unroll
            for (int nt = 0; nt < 4; nt++) {
                int col = wc * 32 + nt * 8 + tid4 * 2;
                float o0 = acc1[nt][mt][half * 2 + 0];
                float o1 = acc1[nt][mt][half * 2 + 1];
                __nv_bfloat162 h = __floats2bfloat162_rn(o0, o1);
                __nv_bfloat162 l = __floats2bfloat162_rn(o0 - __bfloat162float(h.x),
                                                         o1 - __bfloat162float(h.y));
                *(__nv_bfloat162*)(Sh + rl * SAP + col) = h;
                *(__nv_bfloat162*)(Sl + rl * SAP + col) = l;
            }
        }
    __syncthreads();

    {
        int s8[8], d8[8];
        #pragma unroll
        for (int i = 0; i < 8; i++) {
            int er = row0 + w * 8 + i;
            s8[i] = __ldg(src + er);
            d8[i] = __ldg(dst + er);
        }
        #pragma unroll 2
        for (int i = 0; i < 8; i++) {
            int rl = w * 8 + i;
            int s = s8[i], d = d8[i];
            __nv_bfloat162 h0 = *(__nv_bfloat162*)(Sh + rl * SAP + lane * 4);
            __nv_bfloat162 h1 = *(__nv_bfloat162*)(Sh + rl * SAP + lane * 4 + 2);
            __nv_bfloat162 l0 = *(__nv_bfloat162*)(Sl + rl * SAP + lane * 4);
            __nv_bfloat162 l1 = *(__nv_bfloat162*)(Sl + rl * SAP + lane * 4 + 2);
            float4 p;
            p.x = __bfloat162float(h0.x) + __bfloat162float(l0.x);
            p.y = __bfloat162float(h0.y) + __bfloat162float(l0.y);
            p.z = __bfloat162float(h1.x) + __bfloat162float(l1.x);
            p.w = __bfloat162float(h1.y) + __bfloat162float(l1.y);
            float4 q = __ldg((const float4*)(g_Q  + (size_t)d * D) + lane);
            float4 k = __ldg((const float4*)(g_Kb + (size_t)s * D) + lane);
            float4 sc;
            sc.x = k.x * q.x * 0.25f * p.x;
            sc.y = k.y * q.y * 0.25f * p.y;
            sc.z = k.z * q.z * 0.25f * p.z;
            sc.w = k.w * q.w * 0.25f * p.w;
            split_store(Sh, Sl, rl * SAP + lane * 4, sc);
            float part = sc.x + sc.y + sc.z + sc.w;
            part += __shfl_xor_sync(0xffffffffu, part, 1);
            part += __shfl_xor_sync(0xffffffffu, part, 2);
            part  = fminf(fmaxf(part, -5.f), 5.f);
            float sh = expf(part);
            float4 v = __ldg((const float4*)(g_V + (size_t)s * D) + lane);
            float* wv = g_wV + (size_t)d * D + lane * 4;
            asm volatile("red.global.add.v4.f32 [%0], {%1, %2, %3, %4};"
                         :: "l"(wv), "f"(v.x * sh), "f"(v.y * sh), "f"(v.z * sh), "f"(v.w * sh)
                         : "memory");
            if ((lane & 3) == 0) atomicAdd(g_z + (size_t)d * 8 + (lane >> 2), sh);
        }
    }
    __syncthreads();

    float acc2[4][2][4];
    #pragma unroll
    for (int nt = 0; nt < 4; nt++)
        #pragma unroll
        for (int mt = 0; mt < 2; mt++)
            #pragma unroll
            for (int i = 0; i < 4; i++) acc2[nt][mt][i] = 0.f;
    #pragma unroll
    for (int ks = 0; ks < 8; ks++) {
        uint32_t ah[2][4], al[2][4];
        load_afrag_ldsm<SAP>(shSh, shSl, aoff, ks * 32, ah, al);
        #pragma unroll
        for (int ntp = 0; ntp < 2; ntp++) {
            uint4 b0 = __ldg(B2 + ((size_t)ks * 16 + (wc * 4 + ntp * 2 + 0)) * 32 + lane);
            uint4 b1 = __ldg(B2 + ((size_t)ks * 16 + (wc * 4 + ntp * 2 + 1)) * 32 + lane);
            mma_pair(acc2[ntp * 2], acc2[ntp * 2 + 1], ah, al, b0, b1);
        }
    }

    float s1[8], s2[8];
    #pragma unroll
    for (int j = 0; j < 8; j++) { s1[j] = 0.f; s2[j] = 0.f; }
    #pragma unroll
    for (int mt = 0; mt < 2; mt++)
        #pragma unroll
        for (int half = 0; half < 2; half++) {
            int rl = wr * 32 + mt * 16 + g + half * 8;
            int gr = row0 + rl;
            if (gr >= M) continue;
            #pragma unroll
            for (int nt = 0; nt < 4; nt++) {
                int col = wc * 32 + nt * 8 + tid4 * 2;
                float o0 = acc2[nt][mt][half * 2 + 0] + __ldg(bias + col);
                float o1 = acc2[nt][mt][half * 2 + 1] + __ldg(bias + col + 1);
                __nv_bfloat162 rh  = *(__nv_bfloat162*)(Ah + rl * SAP + col);
                __nv_bfloat162 rlo = *(__nv_bfloat162*)(Al + rl * SAP + col);
                o0 += __bfloat162float(rh.x) + __bfloat162float(rlo.x);
                o1 += __bfloat162float(rh.y) + __bfloat162float(rlo.y);
                s1[nt * 2 + 0] += o0; s2[nt * 2 + 0] = fmaf(o0, o0, s2[nt * 2 + 0]);
                s1[nt * 2 + 1] += o1; s2[nt * 2 + 1] = fmaf(o1, o1, s2[nt * 2 + 1]);
                *(float2*)(C + (size_t)gr * 128 + col) = make_float2(o0, o1);
            }
        }
    #pragma unroll
    for (int j = 0; j < 8; j++) {
        float a = s1[j], q = s2[j];
        a += __shfl_xor_sync(0xffffffffu, a, 4);  q += __shfl_xor_sync(0xffffffffu, q, 4);
        a += __shfl_xor_sync(0xffffffffu, a, 8);  q += __shfl_xor_sync(0xffffffffu, q, 8);
        a += __shfl_xor_sync(0xffffffffu, a, 16); q += __shfl_xor_sync(0xffffffffu, q, 16);
        if (g == 0) {
            int col = wc * 32 + (j >> 1) * 8 + tid4 * 2 + (j & 1);
            atomicAdd(stats + col, a);
            atomicAdd(stats + 128 + col, q);
        }
    }
}

// ---------------- combined fused FFN (2 CTA/SM, B prefetch) ----------------
__global__ void __launch_bounds__(256, 2)
ffn_k(const float* __restrict__ Xh, const float* __restrict__ Xe,
      const __nv_bfloat16* __restrict__ W1h, const __nv_bfloat16* __restrict__ W1e,
      const float* __restrict__ b1h, const float* __restrict__ b1e,
      const __nv_bfloat16* __restrict__ W2h, const __nv_bfloat16* __restrict__ W2e,
      const float* __restrict__ b2h, const float* __restrict__ b2e,
      const float* __restrict__ bnab_h, const float* __restrict__ bnab_e,
      float* __restrict__ stats_h, float* __restrict__ stats_e,
      float* __restrict__ Ch, float* __restrict__ Ce, int gNh)
{
    constexpr int SAP = 136, MP = 264;
    extern __shared__ __nv_bfloat16 sm[];
    __nv_bfloat16* Ah = sm;
    __nv_bfloat16* Al = sm + 64 * SAP;
    __nv_bfloat16* Mh = sm;
    __nv_bfloat16* Ml = sm + 64 * MP;

    const int bid = blockIdx.x;
    const float* X; const __nv_bfloat16 *W1img, *W2img;
    const float *b1, *b2, *bnab; float *stats, *C;
    int M, row0;
    if (bid < gNh) {
        X = Xh; W1img = W1h; W2img = W2h; b1 = b1h; b2 = b2h;
        bnab = bnab_h; stats = stats_h; C = Ch; M = NN; row0 = bid * 64;
    } else {
        X = Xe; W1img = W1e; W2img = W2e; b1 = b1e; b2 = b2e;
        bnab = bnab_e; stats = stats_e; C = Ce; M = NE; row0 = (bid - gNh) * 64;
    }

    const int tid  = threadIdx.x;
    const int w    = tid >> 5, lane = tid & 31;
    const int wr   = w >> 2, wc = w & 3;
    const int g    = lane >> 2, tid4 = lane & 3;

    const uint4* B1 = (const uint4*)W1img;
    const uint4* B2 = (const uint4*)W2img;

    #pragma unroll 2
    for (int i = tid; i < 2048; i += 256) {
        int r = i >> 5, c4 = i & 31, col = c4 * 4;
        float4 v = make_float4(0.f, 0.f, 0.f, 0.f);
        int gr = row0 + r;
        if (gr < M) {
            v = __ldg((const float4*)(X + (size_t)gr * 128) + c4);
            v.x = fmaf(v.x, __ldg(bnab + col + 0), __ldg(bnab + 128 + col + 0));
            v.y = fmaf(v.y, __ldg(bnab + col + 1), __ldg(bnab + 128 + col + 1));
            v.z = fmaf(v.z, __ldg(bnab + col + 2), __ldg(bnab + 128 + col + 2));
            v.w = fmaf(v.w, __ldg(bnab + col + 3), __ldg(bnab + 128 + col + 3));
        }
        split_store(Ah, Al, r * SAP + col, v);
    }
    __syncthreads();

    const uint32_t shAh = (uint32_t)__cvta_generic_to_shared(Ah);
    const uint32_t shAl = (uint32_t)__cvta_generic_to_shared(Al);
    const uint32_t shMh = (uint32_t)__cvta_generic_to_shared(Mh);
    const uint32_t shMl = (uint32_t)__cvta_generic_to_shared(Ml);
    const uint32_t aoffA = ldsm_off<SAP>(wr * 32, lane);
    const uint32_t aoffM = ldsm_off<MP>(wr * 32, lane);

    float acc1[8][2][4];
    #pragma unroll
    for (int nt = 0; nt < 8; nt++)
        #pragma unroll
        for (int mt = 0; mt < 2; mt++)
            #pragma unroll
            for (int i = 0; i < 4; i++) acc1[nt][mt][i] = 0.f;

    // FFN1 mainloop with B double-buffer
    {
        uint4 nb0 = __ldg(B1 + ((size_t)(wc * 8 + 0)) * 32 + lane);
        uint4 nb1 = __ldg(B1 + ((size_t)(wc * 8 + 1)) * 32 + lane);
        #pragma unroll
        for (int ks = 0; ks < 8; ks++) {
            uint32_t ah[2][4], al[2][4];
            load_afrag_ldsm<SAP>(shAh, shAl, aoffA, ks * 32, ah, al);
            #pragma unroll
            for (int ntp = 0; ntp < 4; ntp++) {
                uint4 c0 = nb0, c1 = nb1;
                if (!(ks == 7 && ntp == 3)) {
                    int nks = (ntp == 3) ? ks + 1 : ks;
                    int nntp = (ntp == 3) ? 0 : ntp + 1;
                    nb0 = __ldg(B1 + ((size_t)nks * 32 + (wc * 8 + nntp * 2 + 0)) * 32 + lane);
                    nb1 = __ldg(B1 + ((size_t)nks * 32 + (wc * 8 + nntp * 2 + 1)) * 32 + lane);
                }
                mma_pair(acc1[ntp * 2], acc1[ntp * 2 + 1], ah, al, c0, c1);
            }
        }
    }
    __syncthreads();

    #pragma unroll
    for (int mt = 0; mt < 2; mt++)
        #pragma unroll
        for (int half = 0; half < 2; half++) {
            int rl = wr * 32 + mt * 16 + g + half * 8;
            #pragma unroll
            for (int nt = 0; nt < 8; nt++) {
                int col = wc * 64 + nt * 8 + tid4 * 2;
                float o0 = fmaxf(acc1[nt][mt][half * 2 + 0] + __ldg(b1 + col), 0.f);
                float o1 = fmaxf(acc1[nt][mt][half * 2 + 1] + __ldg(b1 + col + 1), 0.f);
                __nv_bfloat162 h = __floats2bfloat162_rn(o0, o1);
                __nv_bfloat162 l = __floats2bfloat162_rn(o0 - __bfloat162float(h.x),
                                                         o1 - __bfloat162float(h.y));
                *(__nv_bfloat162*)(Mh + rl * MP + col) = h;
                *(__nv_bfloat162*)(Ml + rl * MP + col) = l;
            }
        }
    __syncthreads();

    float acc2[4][2][4];
    #pragma unroll
    for (int nt = 0; nt < 4; nt++)
        #pragma unroll
        for (int mt = 0; mt < 2; mt++)
            #pragma unroll
            for (int i = 0; i < 4; i++) acc2[nt][mt][i] = 0.f;

    // FFN2 mainloop with B double-buffer
    {
        uint4 nb0 = __ldg(B2 + ((size_t)(wc * 4 + 0)) * 32 + lane);
        uint4 nb1 = __ldg(B2 + ((size_t)(wc * 4 + 1)) * 32 + lane);
        #pragma unroll
        for (int ks = 0; ks < 16; ks++) {
            uint32_t ah[2][4], al[2][4];
            load_afrag_ldsm<MP>(shMh, shMl, aoffM, ks * 32, ah, al);
            #pragma unroll
            for (int ntp = 0; ntp < 2; ntp++) {
                uint4 c0 = nb0, c1 = nb1;
                if (!(ks == 15 && ntp == 1)) {
                    int nks = (ntp == 1) ? ks + 1 : ks;
                    int nntp = (ntp == 1) ? 0 : 1;
                    nb0 = __ldg(B2 + ((size_t)nks * 16 + (wc * 4 + nntp * 2 + 0)) * 32 + lane);
                    nb1 = __ldg(B2 + ((size_t)nks * 16 + (wc * 4 + nntp * 2 + 1)) * 32 + lane);
                }
                mma_pair(acc2[ntp * 2], acc2[ntp * 2 + 1], ah, al, c0, c1);
            }
        }
    }

    float s1[8], s2[8];
    #pragma unroll
    for (int j = 0; j < 8; j++) { s1[j] = 0.f; s2[j] = 0.f; }
    #pragma unroll
    for (int mt = 0; mt < 2; mt++)
        #pragma unroll
        for (int half = 0; half < 2; half++) {
            int gr = row0 + wr * 32 + mt * 16 + g + half * 8;
            if (gr >= M) continue;
            #pragma unroll
            for (int nt = 0; nt < 4; nt++) {
                int col = wc * 32 + nt * 8 + tid4 * 2;
                float o0 = acc2[nt][mt][half * 2 + 0] + __ldg(b2 + col);
                float o1 = acc2[nt][mt][half * 2 + 1] + __ldg(b2 + col + 1);
                float2 rv = __ldg((const float2*)(X + (size_t)gr * 128 + col));
                o0 = fmaf(rv.x, __ldg(bnab + col),     o0 + __ldg(bnab + 128 + col));
                o1 = fmaf(rv.y, __ldg(bnab + col + 1), o1 + __ldg(bnab + 128 + col + 1));
                s1[nt * 2 + 0] += o0; s2[nt * 2 + 0] = fmaf(o0, o0, s2[nt * 2 + 0]);
                s1[nt * 2 + 1] += o1; s2[nt * 2 + 1] = fmaf(o1, o1, s2[nt * 2 + 1]);
                *(float2*)(C + (size_t)gr * 128 + col) = make_float2(o0, o1);
            }
        }
    #pragma unroll
    for (int j = 0; j < 8; j++) {
        float a = s1[j], q = s2[j];
        a += __shfl_xor_sync(0xffffffffu, a, 4);  q += __shfl_xor_sync(0xffffffffu, q, 4);
        a += __shfl_xor_sync(0xffffffffu, a, 8);  q += __shfl_xor_sync(0xffffffffu, q, 8);
        a += __shfl_xor_sync(0xffffffffu, a, 16); q += __shfl_xor_sync(0xffffffffu, q, 16);
        if (g == 0) {
            int col = wc * 32 + (j >> 1) * 8 + tid4 * 2 + (j & 1);
            atomicAdd(stats + col, a);
            atomicAdd(stats + 128 + col, q);
        }
    }
}

// ---------------- merged finalize ----------------
__global__ void finalize_bn2(int bnA, const float* __restrict__ gA, const float* __restrict__ bA, float minvA,
                             int bnB, const float* __restrict__ gB, const float* __restrict__ bB, float minvB)
{
    int c = threadIdx.x;
    int bn; const float *g, *b; float minv;
    if (blockIdx.x == 0) { bn = bnA; g = gA; b = bA; minv = minvA; }
    else                 { bn = bnB; g = gB; b = bB; minv = minvB; }
    float mean = g_stats[bn * 2 * D + c] * minv;
    float var  = g_stats[bn * 2 * D + D + c] * minv - mean * mean;
    float rstd = rsqrtf(var + 1e-5f);
    float scv  = g[c] * rstd;
    g_bnab[bn * 2 * D + c]     = scv;
    g_bnab[bn * 2 * D + D + c] = b[c] - mean * scv;
}

// ---------------- vectorized output BN ----------------
__global__ void out_norm(float4* __restrict__ out)
{
    size_t i = (size_t)blockIdx.x * blockDim.x + threadIdx.x;
    if (i >= (size_t)(NN + NE) * 32) return;
    int c4 = (int)(i & 31) * 4;
    int bn = (i < (size_t)NN * 32) ? 2 : 3;
    const float* ab = g_bnab + bn * 2 * D;
    float4 v = out[i];
    v.x = fmaf(v.x, ab[c4 + 0], ab[128 + c4 + 0]);
    v.y = fmaf(v.y, ab[c4 + 1], ab[128 + c4 + 1]);
    v.z = fmaf(v.z, ab[c4 + 2], ab[128 + c4 + 2]);
    v.w = fmaf(v.w, ab[c4 + 3], ab[128 + c4 + 3]);
    out[i] = v;
}

// ---------------- host ----------------
extern "C" void kernel_launch(void* const* d_in, const int* in_sizes, int n_in,
                              void* d_out, int out_size)
{
    (void)in_sizes; (void)n_in; (void)out_size;
    const float* h_in  = (const float*)d_in[0];
    const float* e_in  = (const float*)d_in[1];
    const float* Wq    = (const float*)d_in[2];
    const float* Wk    = (const float*)d_in[3];
    const float* Wv    = (const float*)d_in[4];
    const float* We    = (const float*)d_in[5];
    const float* Ohw   = (const float*)d_in[6];
    const float* Ohb   = (const float*)d_in[7];
    const float* Oew   = (const float*)d_in[8];
    const float* Oeb   = (const float*)d_in[9];
    const float* bn1hg = (const float*)d_in[10];
    const float* bn1hb = (const float*)d_in[11];
    const float* bn1eg = (const float*)d_in[12];
    const float* bn1eb = (const float*)d_in[13];
    const float* fhw1  = (const float*)d_in[14];
    const float* fhb1  = (const float*)d_in[15];
    const float* fhw2  = (const float*)d_in[16];
    const float* fhb2  = (const float*)d_in[17];
    const float* few1  = (const float*)d_in[18];
    const float* feb1  = (const float*)d_in[19];
    const float* few2  = (const float*)d_in[20];
    const float* feb2  = (const float*)d_in[21];
    const float* bn2hg = (const float*)d_in[22];
    const float* bn2hb = (const float*)d_in[23];
    const float* bn2eg = (const float*)d_in[24];
    const float* bn2eb = (const float*)d_in[25];
    const int*   src   = (const int*)d_in[26];
    const int*   dst   = (const int*)d_in[27];

    float* out  = (float*)d_out;
    float* outh = out;
    float* oute = out + (size_t)NN * D;

    float *pQ, *pK, *pV, *pwV, *pz, *ph2, *pe2, *pstats, *pbnab;
    __nv_bfloat16* pimg;
    cudaGetSymbolAddress((void**)&pQ,    g_Q);
    cudaGetSymbolAddress((void**)&pK,    g_Kb);
    cudaGetSymbolAddress((void**)&pV,    g_V);
    cudaGetSymbolAddress((void**)&pwV,   g_wV);
    cudaGetSymbolAddress((void**)&pz,    g_z);
    cudaGetSymbolAddress((void**)&ph2,   g_h2);
    cudaGetSymbolAddress((void**)&pe2,   g_e2);
    cudaGetSymbolAddress((void**)&pstats, g_stats);
    cudaGetSymbolAddress((void**)&pbnab,  g_bnab);
    cudaGetSymbolAddress((void**)&pimg,   g_wimg);

    const size_t oWe = 0, oWq = 32768, oWk = 65536, oWv = 98304;
    const size_t oOh = 131072, oOe = 163840;
    const size_t oF1h = 196608, oF1e = 262144, oF2h = 327680, oF2e = 393216;

    auto kBh = mm_k<1, 1, 1, 1>;

    const int SMEM_64 = 2 * 64 * 136 * 2;    // 34816
    const int SMEM_E  = 4 * 64 * 136 * 2;    // 69632
    const int SMEM_F  = 2 * 64 * 264 * 2;    // 67584
    cudaFuncSetAttribute(kBh,   cudaFuncAttributeMaxDynamicSharedMemorySize, SMEM_64);
    cudaFuncSetAttribute(qkv_k, cudaFuncAttributeMaxDynamicSharedMemorySize, SMEM_64);
    cudaFuncSetAttribute(epj_k, cudaFuncAttributeMaxDynamicSharedMemorySize, SMEM_E);
    cudaFuncSetAttribute(ffn_k, cudaFuncAttributeMaxDynamicSharedMemorySize, SMEM_F);

    const int gN64 = (NN + 63) / 64;
    const int gE64 = (NE + 63) / 64;

    cudaMemsetAsync(pwV,    0, sizeof(float) * NN * D);
    cudaMemsetAsync(pz,     0, sizeof(float) * NN * 8);
    cudaMemsetAsync(pstats, 0, sizeof(float) * 4 * 2 * D);

    PrepArgs pa;
    pa.src[0] = We;   pa.src[1] = Wq;   pa.src[2] = Wk;   pa.src[3] = Wv;
    pa.src[4] = Ohw;  pa.src[5] = Oew;
    pa.src[6] = fhw1; pa.src[7] = few1; pa.src[8] = fhw2; pa.src[9] = few2;
    prep_all<<<(229376 + 255) / 256, 256>>>(pa, pimg);

    qkv_k<<<dim3(1, gN64), 256, SMEM_64>>>(h_in, pimg + oWq, pimg + oWk, pimg + oWv, pQ, pK, pV, NN);

    epj_k<<<gE64, 256, SMEM_E>>>(e_in, pimg + oWe, pimg + oOe, Oeb, src, dst,
                                 pstats + 1 * 2 * D, pe2, NE);

    kBh<<<dim3(1, gN64), 256, SMEM_64>>>(pwV, pimg + oOh, Ohb, h_in, nullptr, pz,
                                         pstats + 0 * 2 * D, ph2, NN);

    finalize_bn2<<<2, D>>>(0, bn1hg, bn1hb, 1.f / NN, 1, bn1eg, bn1eb, 1.f / NE);

    ffn_k<<<gN64 + gE64, 256, SMEM_F>>>(ph2, pe2,
                                        pimg + oF1h, pimg + oF1e, fhb1, feb1,
                                        pimg + oF2h, pimg + oF2e, fhb2, feb2,
                                        pbnab + 0 * 2 * D, pbnab + 1 * 2 * D,
                                        pstats + 2 * 2 * D, pstats + 3 * 2 * D,
                                        outh, oute, gN64);

    finalize_bn2<<<2, D>>>(2, bn2hg, bn2hb, 1.f / NN, 3, bn2eg, bn2eb, 1.f / NE);

    out_norm<<<(int)(((size_t)(NN + NE) * 32 + 255) / 256), 256>>>((float4*)out);
}

// round 16
// speedup vs baseline: 1.0726x; 1.0726x over previous
#include <cuda_runtime.h>
#include <cuda_bf16.h>
#include <math.h>
#include <stdint.h>

#define NN 50000
#define NE 800000
#define D  128

// ---------------- scratch ----------------
static __device__ float g_Q  [NN * D];
static __device__ float g_Kb [NN * D];
static __device__ float g_V  [NN * D];
static __device__ float g_wV [NN * D];
static __device__ float g_z  [NN * 8];
static __device__ float g_h2 [NN * D];
static __device__ float g_e2 [(size_t)NE * D];
static __device__ float g_stats[4 * 2 * D];
static __device__ float g_bnab [4 * 2 * D];
static __device__ __nv_bfloat16 g_wimg[458752];

// ---------------- merged weight prep ----------------
struct PrepArgs { const float* src[10]; };

__global__ void prep_all(PrepArgs args, __nv_bfloat16* __restrict__ img)
{
    int idx = blockIdx.x * blockDim.x + threadIdx.x;
    if (idx >= 229376) return;
    int w, off, K, N;
    size_t ooff;
    if (idx < 98304) {
        w = idx >> 14; off = idx & 16383; K = 128; N = 128;
        ooff = (size_t)w * 32768;
    } else {
        int t = idx - 98304;
        w = 6 + (t >> 15); off = t & 32767;
        if (w < 8) { K = 128; N = 256; } else { K = 256; N = 128; }
        ooff = 196608 + (size_t)(w - 6) * 65536;
    }
    const float* W = args.src[w];
    int k = off / N, n = off - k * N;
    float wv = __ldg(W + off);
    __nv_bfloat16 hi = __float2bfloat16(wv);
    __nv_bfloat16 lo = __float2bfloat16(wv - __bfloat162float(hi));
    int kstep = k >> 4, kin = k & 15;
    int reg  = (kin >> 3) & 1;
    int tid4 = (kin >> 1) & 3;
    int p    = kin & 1;
    int gg   = n & 7;
    int ntile = n >> 3;
    int lane = gg * 4 + tid4;
    size_t idx4 = ((size_t)kstep * (N >> 3) + ntile) * 32 + lane;
    img[ooff + idx4 * 8 + reg * 2 + p]     = hi;
    img[ooff + idx4 * 8 + 4 + reg * 2 + p] = lo;
}

__device__ __forceinline__ void mma16816(float* c, const uint32_t* a, uint32_t b0, uint32_t b1)
{
    asm volatile(
        "mma.sync.aligned.m16n8k16.row.col.f32.bf16.bf16.f32 "
        "{%0,%1,%2,%3}, {%4,%5,%6,%7}, {%8,%9}, {%0,%1,%2,%3};"
        : "+f"(c[0]), "+f"(c[1]), "+f"(c[2]), "+f"(c[3])
        : "r"(a[0]), "r"(a[1]), "r"(a[2]), "r"(a[3]), "r"(b0), "r"(b1));
}

__device__ __forceinline__ void ldsm4(uint32_t r[4], uint32_t addr)
{
    asm volatile("ldmatrix.sync.aligned.m8n8.x4.shared.b16 {%0,%1,%2,%3}, [%4];"
                 : "=r"(r[0]), "=r"(r[1]), "=r"(r[2]), "=r"(r[3]) : "r"(addr));
}

template<int STRIDE>
__device__ __forceinline__ uint32_t ldsm_off(int r0, int lane)
{
    int row = r0 + (lane & 7) + ((lane >> 3) & 1) * 8;
    int col = ((lane >> 4) & 1) * 8;
    return (uint32_t)((row * STRIDE + col) * 2);
}

template<int STRIDE>
__device__ __forceinline__ void load_afrag_ldsm(uint32_t shH, uint32_t shL, uint32_t aoff,
                                                uint32_t ksbyte, uint32_t ah[2][4], uint32_t al[2][4])
{
    ldsm4(ah[0], shH + aoff + ksbyte);
    ldsm4(ah[1], shH + aoff + ksbyte + 16 * STRIDE * 2);
    ldsm4(al[0], shL + aoff + ksbyte);
    ldsm4(al[1], shL + aoff + ksbyte + 16 * STRIDE * 2);
}

__device__ __forceinline__ void split_store(__nv_bfloat16* Ah, __nv_bfloat16* Al,
                                            int off, float4 v)
{
    __nv_bfloat162 h0 = __floats2bfloat162_rn(v.x, v.y);
    __nv_bfloat162 h1 = __floats2bfloat162_rn(v.z, v.w);
    __nv_bfloat162 l0 = __floats2bfloat162_rn(v.x - __bfloat162float(h0.x),
                                              v.y - __bfloat162float(h0.y));
    __nv_bfloat162 l1 = __floats2bfloat162_rn(v.z - __bfloat162float(h1.x),
                                              v.w - __bfloat162float(h1.y));
    *(__nv_bfloat162*)(Ah + off)     = h0;
    *(__nv_bfloat162*)(Ah + off + 2) = h1;
    *(__nv_bfloat162*)(Al + off)     = l0;
    *(__nv_bfloat162*)(Al + off + 2) = l1;
}

__device__ __forceinline__ void mma_pair(float acc0[2][4], float acc1[2][4],
                                         const uint32_t ah[2][4], const uint32_t al[2][4],
                                         uint4 b0, uint4 b1)
{
    mma16816(acc0[0], ah[0], b0.x, b0.y);
    mma16816(acc0[1], ah[1], b0.x, b0.y);
    mma16816(acc1[0], ah[0], b1.x, b1.y);
    mma16816(acc1[1], ah[1], b1.x, b1.y);
    mma16816(acc0[0], ah[0], b0.z, b0.w);
    mma16816(acc0[1], ah[1], b0.z, b0.w);
    mma16816(acc1[0], ah[0], b1.z, b1.w);
    mma16816(acc1[1], ah[1], b1.z, b1.w);
    mma16816(acc0[0], al[0], b0.x, b0.y);
    mma16816(acc0[1], al[1], b0.x, b0.y);
    mma16816(acc1[0], al[0], b1.x, b1.y);
    mma16816(acc1[1], al[1], b1.x, b1.y);
}

// ---------------- h-side O-proj GEMM, 64-row tiles, 3 CTA/SM ----------------
template<int BIAS, int RESM, int DO_STATS, int DIVZ>
__global__ void __launch_bounds__(256, 3)
mm_k(const float* __restrict__ X, const __nv_bfloat16* __restrict__ Wimg,
     const float* __restrict__ bias, const float* __restrict__ res,
     const float* __restrict__ res_ab,
     const float* __restrict__ zdiv, float* __restrict__ stats,
     float* __restrict__ C, int M)
{
    constexpr int SAP = 136;
    extern __shared__ __nv_bfloat16 sA[];
    __nv_bfloat16* Ah = sA;
    __nv_bfloat16* Al = sA + 64 * SAP;

    const int tid  = threadIdx.x;
    const int w    = tid >> 5, lane = tid & 31;
    const int wr   = w >> 2, wc = w & 3;
    const int g    = lane >> 2, tid4 = lane & 3;
    const int row0 = blockIdx.y * 64;

    const uint4* Bimg = (const uint4*)Wimg;

    float acc[4][2][4];
    #pragma unroll
    for (int nt = 0; nt < 4; nt++)
        #pragma unroll
        for (int mt = 0; mt < 2; mt++)
            #pragma unroll
            for (int i = 0; i < 4; i++) acc[nt][mt][i] = 0.f;

    #pragma unroll 2
    for (int i = tid; i < 2048; i += 256) {
        int r = i >> 5, c4 = i & 31, col = c4 * 4;
        float4 v = make_float4(0.f, 0.f, 0.f, 0.f);
        int gr = row0 + r;
        if (gr < M) {
            v = __ldg((const float4*)(X + (size_t)gr * 128) + c4);
            if (DIVZ) {
                float inv = 1.0f / (__ldg(zdiv + gr * 8 + (c4 >> 2)) + 1e-6f);
                v.x *= inv; v.y *= inv; v.z *= inv; v.w *= inv;
            }
        }
        split_store(Ah, Al, r * SAP + col, v);
    }
    __syncthreads();

    const uint32_t shAh = (uint32_t)__cvta_generic_to_shared(Ah);
    const uint32_t shAl = (uint32_t)__cvta_generic_to_shared(Al);
    const uint32_t aoff = ldsm_off<SAP>(wr * 32, lane);

    #pragma unroll
    for (int ks = 0; ks < 8; ks++) {
        uint32_t ah[2][4], al[2][4];
        load_afrag_ldsm<SAP>(shAh, shAl, aoff, ks * 32, ah, al);
        #pragma unroll
        for (int ntp = 0; ntp < 2; ntp++) {
            uint4 b0 = __ldg(Bimg + ((size_t)ks * 16 + (wc * 4 + ntp * 2 + 0)) * 32 + lane);
            uint4 b1 = __ldg(Bimg + ((size_t)ks * 16 + (wc * 4 + ntp * 2 + 1)) * 32 + lane);
            mma_pair(acc[ntp * 2], acc[ntp * 2 + 1], ah, al, b0, b1);
        }
    }

    float s1[8], s2[8];
    if (DO_STATS) {
        #pragma unroll
        for (int j = 0; j < 8; j++) { s1[j] = 0.f; s2[j] = 0.f; }
    }
    #pragma unroll
    for (int mt = 0; mt < 2; mt++)
        #pragma unroll
        for (int half = 0; half < 2; half++) {
            int gr = row0 + wr * 32 + mt * 16 + g + half * 8;
            if (gr >= M) continue;
            #pragma unroll
            for (int nt = 0; nt < 4; nt++) {
                int col = wc * 32 + nt * 8 + tid4 * 2;
                float o0 = acc[nt][mt][half * 2 + 0];
                float o1 = acc[nt][mt][half * 2 + 1];
                if (BIAS) { o0 += __ldg(bias + col); o1 += __ldg(bias + col + 1); }
                if (RESM) {
                    float2 rv = __ldg((const float2*)(res + (size_t)gr * D + col));
                    o0 += rv.x; o1 += rv.y;
                }
                if (DO_STATS) {
                    s1[nt * 2 + 0] += o0; s2[nt * 2 + 0] = fmaf(o0, o0, s2[nt * 2 + 0]);
                    s1[nt * 2 + 1] += o1; s2[nt * 2 + 1] = fmaf(o1, o1, s2[nt * 2 + 1]);
                }
                *(float2*)(C + (size_t)gr * D + col) = make_float2(o0, o1);
            }
        }
    if (DO_STATS) {
        #pragma unroll
        for (int j = 0; j < 8; j++) {
            float a = s1[j], q = s2[j];
            a += __shfl_xor_sync(0xffffffffu, a, 4);  q += __shfl_xor_sync(0xffffffffu, q, 4);
            a += __shfl_xor_sync(0xffffffffu, a, 8);  q += __shfl_xor_sync(0xffffffffu, q, 8);
            a += __shfl_xor_sync(0xffffffffu, a, 16); q += __shfl_xor_sync(0xffffffffu, q, 16);
            if (g == 0) {
                int col = wc * 32 + (j >> 1) * 8 + tid4 * 2 + (j & 1);
                atomicAdd(stats + col, a);
                atomicAdd(stats + 128 + col, q);
            }
        }
    }
}

// ---------------- fused QKV, 64-row tiles, 3 CTA/SM ----------------
__global__ void __launch_bounds__(256, 3)
qkv_k(const float* __restrict__ X,
      const __nv_bfloat16* __restrict__ Wq, const __nv_bfloat16* __restrict__ Wk,
      const __nv_bfloat16* __restrict__ Wv,
      float* __restrict__ Cq, float* __restrict__ Ck, float* __restrict__ Cv, int M)
{
    constexpr int SAP = 136;
    extern __shared__ __nv_bfloat16 sA[];
    __nv_bfloat16* Ah = sA;
    __nv_bfloat16* Al = sA + 64 * SAP;

    const int tid  = threadIdx.x;
    const int w    = tid >> 5, lane = tid & 31;
    const int wr   = w >> 2, wc = w & 3;
    const int g    = lane >> 2, tid4 = lane & 3;
    const int row0 = blockIdx.y * 64;

    #pragma unroll 2
    for (int i = tid; i < 2048; i += 256) {
        int r = i >> 5, c4 = i & 31, col = c4 * 4;
        float4 v = make_float4(0.f, 0.f, 0.f, 0.f);
        int gr = row0 + r;
        if (gr < M) v = __ldg((const float4*)(X + (size_t)gr * 128) + c4);
        split_store(Ah, Al, r * SAP + col, v);
    }
    __syncthreads();

    const uint32_t shAh = (uint32_t)__cvta_generic_to_shared(Ah);
    const uint32_t shAl = (uint32_t)__cvta_generic_to_shared(Al);
    const uint32_t aoff = ldsm_off<SAP>(wr * 32, lane);

    const __nv_bfloat16* Ws[3] = {Wq, Wk, Wv};
    float* Cs[3] = {Cq, Ck, Cv};
    #pragma unroll 1
    for (int wsel = 0; wsel < 3; wsel++) {
        const uint4* Bimg = (const uint4*)Ws[wsel];
        float* C = Cs[wsel];
        float acc[4][2][4];
        #pragma unroll
        for (int nt = 0; nt < 4; nt++)
            #pragma unroll
            for (int mt = 0; mt < 2; mt++)
                #pragma unroll
                for (int i = 0; i < 4; i++) acc[nt][mt][i] = 0.f;
        #pragma unroll
        for (int ks = 0; ks < 8; ks++) {
            uint32_t ah[2][4], al[2][4];
            load_afrag_ldsm<SAP>(shAh, shAl, aoff, ks * 32, ah, al);
            #pragma unroll
            for (int ntp = 0; ntp < 2; ntp++) {
                uint4 b0 = __ldg(Bimg + ((size_t)ks * 16 + (wc * 4 + ntp * 2 + 0)) * 32 + lane);
                uint4 b1 = __ldg(Bimg + ((size_t)ks * 16 + (wc * 4 + ntp * 2 + 1)) * 32 + lane);
                mma_pair(acc[ntp * 2], acc[ntp * 2 + 1], ah, al, b0, b1);
            }
        }
        #pragma unroll
        for (int mt = 0; mt < 2; mt++)
            #pragma unroll
            for (int half = 0; half < 2; half++) {
                int gr = row0 + wr * 32 + mt * 16 + g + half * 8;
                if (gr >= M) continue;
                #pragma unroll
                for (int nt = 0; nt < 4; nt++) {
                    int col = wc * 32 + nt * 8 + tid4 * 2;
                    *(float2*)(C + (size_t)gr * D + col) =
                        make_float2(acc[nt][mt][half * 2 + 0], acc[nt][mt][half * 2 + 1]);
                }
            }
    }
}

// ---------------- fused edge pipeline, 2 CTA/SM ----------------
__global__ void __launch_bounds__(256, 2)
epj_k(const float* __restrict__ X, const __nv_bfloat16* __restrict__ W1img,
      const __nv_bfloat16* __restrict__ W2img, const float* __restrict__ bias,
      const int* __restrict__ src, const int* __restrict__ dst,
      float* __restrict__ stats, float* __restrict__ C, int M)
{
    constexpr int SAP = 136;
    extern __shared__ __nv_bfloat16 sm[];
    __nv_bfloat16* Ah = sm;
    __nv_bfloat16* Al = sm + 64 * SAP;
    __nv_bfloat16* Sh = sm + 2 * 64 * SAP;
    __nv_bfloat16* Sl = sm + 3 * 64 * SAP;

    const int tid  = threadIdx.x;
    const int w    = tid >> 5, lane = tid & 31;
    const int wr   = w >> 2, wc = w & 3;
    const int g    = lane >> 2, tid4 = lane & 3;
    const int row0 = blockIdx.x * 64;

    const uint4* B1 = (const uint4*)W1img;
    const uint4* B2 = (const uint4*)W2img;

    #pragma unroll 2
    for (int i = tid; i < 2048; i += 256) {
        int r = i >> 5, c4 = i & 31, col = c4 * 4;
        float4 v = make_float4(0.f, 0.f, 0.f, 0.f);
        int gr = row0 + r;
        if (gr < M) v = __ldg((const float4*)(X + (size_t)gr * 128) + c4);
        split_store(Ah, Al, r * SAP + col, v);
    }
    __syncthreads();

    const uint32_t shAh = (uint32_t)__cvta_generic_to_shared(Ah);
    const uint32_t shAl = (uint32_t)__cvta_generic_to_shared(Al);
    const uint32_t shSh = (uint32_t)__cvta_generic_to_shared(Sh);
    const uint32_t shSl = (uint32_t)__cvta_generic_to_shared(Sl);
    const uint32_t aoff = ldsm_off<SAP>(wr * 32, lane);

    float acc1[4][2][4];
    #pragma unroll
    for (int nt = 0; nt < 4; nt++)
        #pragma unroll
        for (int mt = 0; mt < 2; mt++)
            #pragma unroll
            for (int i = 0; i < 4; i++) acc1[nt][mt][i] = 0.f;
    #pragma unroll
    for (int ks = 0; ks < 8; ks++) {
        uint32_t ah[2][4], al[2][4];
        load_afrag_ldsm<SAP>(shAh, shAl, aoff, ks * 32, ah, al);
        #pragma unroll
        for (int ntp = 0; ntp < 2; ntp++) {
            uint4 b0 = __ldg(B1 + ((size_t)ks * 16 + (wc * 4 + ntp * 2 + 0)) * 32 + lane);
            uint4 b1 = __ldg(B1 + ((size_t)ks * 16 + (wc * 4 + ntp * 2 + 1)) * 32 + lane);
            mma_pair(acc1[ntp * 2], acc1[ntp * 2 + 1], ah, al, b0, b1);
        }
    }
    #pragma unroll
    for (int mt = 0; mt < 2; mt++)
        #pragma unroll
        for (int half = 0; half < 2; half++) {
            int rl = wr * 32 + mt * 16 + g + half * 8;
            #pragma unroll
            for (int nt = 0; nt < 4; nt++) {
                int col = wc * 32 + nt * 8 + tid4 * 2;
                float o0 = acc1[nt][mt][half * 2 + 0];
                float o1 = acc1[nt][mt][half * 2 + 1];
                __nv_bfloat162 h = __floats2bfloat162_rn(o0, o1);
                __nv_bfloat162 l = __floats2bfloat162_rn(o0 - __bfloat162float(h.x),
                                                         o1 - __bfloat162float(h.y));
                *(__nv_bfloat162*)(Sh + rl * SAP + col) = h;
                *(__nv_bfloat162*)(Sl + rl * SAP + col) = l;
            }
        }
    __syncthreads();

    {
        int s8[8], d8[8];
        #pragma unroll
        for (int i = 0; i < 8; i++) {
            int er = row0 + w * 8 + i;
            s8[i] = __ldg(src + er);
            d8[i] = __ldg(dst + er);
        }
        #pragma unroll 2
        for (int i = 0; i < 8; i++) {
            int rl = w * 8 + i;
            int s = s8[i], d = d8[i];
            __nv_bfloat162 h0 = *(__nv_bfloat162*)(Sh + rl * SAP + lane * 4);
            __nv_bfloat162 h1 = *(__nv_bfloat162*)(Sh + rl * SAP + lane * 4 + 2);
            __nv_bfloat162 l0 = *(__nv_bfloat162*)(Sl + rl * SAP + lane * 4);
            __nv_bfloat162 l1 = *(__nv_bfloat162*)(Sl + rl * SAP + lane * 4 + 2);
            float4 p;
            p.x = __bfloat162float(h0.x) + __bfloat162float(l0.x);
            p.y = __bfloat162float(h0.y) + __bfloat162float(l0.y);
            p.z = __bfloat162float(h1.x) + __bfloat162float(l1.x);
            p.w = __bfloat162float(h1.y) + __bfloat162float(l1.y);
            float4 q = __ldg((const float4*)(g_Q  + (size_t)d * D) + lane);
            float4 k = __ldg((const float4*)(g_Kb + (size_t)s * D) + lane);
            float4 sc;
            sc.x = k.x * q.x * 0.25f * p.x;
            sc.y = k.y * q.y * 0.25f * p.y;
            sc.z = k.z * q.z * 0.25f * p.z;
            sc.w = k.w * q.w * 0.25f * p.w;
            split_store(Sh, Sl, rl * SAP + lane * 4, sc);
            float part = sc.x + sc.y + sc.z + sc.w;
            part += __shfl_xor_sync(0xffffffffu, part, 1);
            part += __shfl_xor_sync(0xffffffffu, part, 2);
            part  = fminf(fmaxf(part, -5.f), 5.f);
            float sh = expf(part);
            float4 v = __ldg((const float4*)(g_V + (size_t)s * D) + lane);
            float* wv = g_wV + (size_t)d * D + lane * 4;
            asm volatile("red.global.add.v4.f32 [%0], {%1, %2, %3, %4};"
                         :: "l"(wv), "f"(v.x * sh), "f"(v.y * sh), "f"(v.z * sh), "f"(v.w * sh)
                         : "memory");
            if ((lane & 3) == 0) atomicAdd(g_z + (size_t)d * 8 + (lane >> 2), sh);
        }
    }
    __syncthreads();

    float acc2[4][2][4];
    #pragma unroll
    for (int nt = 0; nt < 4; nt++)
        #pragma unroll
        for (int mt = 0; mt < 2; mt++)
            #pragma unroll
            for (int i = 0; i < 4; i++) acc2[nt][mt][i] = 0.f;
    #pragma unroll
    for (int ks = 0; ks < 8; ks++) {
        uint32_t ah[2][4], al[2][4];
        load_afrag_ldsm<SAP>(shSh, shSl, aoff, ks * 32, ah, al);
        #pragma unroll
        for (int ntp = 0; ntp < 2; ntp++) {
            uint4 b0 = __ldg(B2 + ((size_t)ks * 16 + (wc * 4 + ntp * 2 + 0)) * 32 + lane);
            uint4 b1 = __ldg(B2 + ((size_t)ks * 16 + (wc * 4 + ntp * 2 + 1)) * 32 + lane);
            mma_pair(acc2[ntp * 2], acc2[ntp * 2 + 1], ah, al, b0, b1);
        }
    }

    float s1[8], s2[8];
    #pragma unroll
    for (int j = 0; j < 8; j++) { s1[j] = 0.f; s2[j] = 0.f; }
    #pragma unroll
    for (int mt = 0; mt < 2; mt++)
        #pragma unroll
        for (int half = 0; half < 2; half++) {
            int rl = wr * 32 + mt * 16 + g + half * 8;
            int gr = row0 + rl;
            if (gr >= M) continue;
            #pragma unroll
            for (int nt = 0; nt < 4; nt++) {
                int col = wc * 32 + nt * 8 + tid4 * 2;
                float o0 = acc2[nt][mt][half * 2 + 0] + __ldg(bias + col);
                float o1 = acc2[nt][mt][half * 2 + 1] + __ldg(bias + col + 1);
                __nv_bfloat162 rh  = *(__nv_bfloat162*)(Ah + rl * SAP + col);
                __nv_bfloat162 rlo = *(__nv_bfloat162*)(Al + rl * SAP + col);
                o0 += __bfloat162float(rh.x) + __bfloat162float(rlo.x);
                o1 += __bfloat162float(rh.y) + __bfloat162float(rlo.y);
                s1[nt * 2 + 0] += o0; s2[nt * 2 + 0] = fmaf(o0, o0, s2[nt * 2 + 0]);
                s1[nt * 2 + 1] += o1; s2[nt * 2 + 1] = fmaf(o1, o1, s2[nt * 2 + 1]);
                *(float2*)(C + (size_t)gr * 128 + col) = make_float2(o0, o1);
            }
        }
    #pragma unroll
    for (int j = 0; j < 8; j++) {
        float a = s1[j], q = s2[j];
        a += __shfl_xor_sync(0xffffffffu, a, 4);  q += __shfl_xor_sync(0xffffffffu, q, 4);
        a += __shfl_xor_sync(0xffffffffu, a, 8);  q += __shfl_xor_sync(0xffffffffu, q, 8);
        a += __shfl_xor_sync(0xffffffffu, a, 16); q += __shfl_xor_sync(0xffffffffu, q, 16);
        if (g == 0) {
            int col = wc * 32 + (j >> 1) * 8 + tid4 * 2 + (j & 1);
            atomicAdd(stats + col, a);
            atomicAdd(stats + 128 + col, q);
        }
    }
}

// ---------------- combined fused FFN (2 CTA/SM) ----------------
__global__ void __launch_bounds__(256, 2)
ffn_k(const float* __restrict__ Xh, const float* __restrict__ Xe,
      const __nv_bfloat16* __restrict__ W1h, const __nv_bfloat16* __restrict__ W1e,
      const float* __restrict__ b1h, const float* __restrict__ b1e,
      const __nv_bfloat16* __restrict__ W2h, const __nv_bfloat16* __restrict__ W2e,
      const float* __restrict__ b2h, const float* __restrict__ b2e,
      const float* __restrict__ bnab_h, const float* __restrict__ bnab_e,
      float* __restrict__ stats_h, float* __restrict__ stats_e,
      float* __restrict__ Ch, float* __restrict__ Ce, int gNh)
{
    constexpr int SAP = 136, MP = 264;
    extern __shared__ __nv_bfloat16 sm[];
    __nv_bfloat16* Ah = sm;
    __nv_bfloat16* Al = sm + 64 * SAP;
    __nv_bfloat16* Mh = sm;
    __nv_bfloat16* Ml = sm + 64 * MP;

    const int bid = blockIdx.x;
    const float* X; const __nv_bfloat16 *W1img, *W2img;
    const float *b1, *b2, *bnab; float *stats, *C;
    int M, row0;
    if (bid < gNh) {
        X = Xh; W1img = W1h; W2img = W2h; b1 = b1h; b2 = b2h;
        bnab = bnab_h; stats = stats_h; C = Ch; M = NN; row0 = bid * 64;
    } else {
        X = Xe; W1img = W1e; W2img = W2e; b1 = b1e; b2 = b2e;
        bnab = bnab_e; stats = stats_e; C = Ce; M = NE; row0 = (bid - gNh) * 64;
    }

    const int tid  = threadIdx.x;
    const int w    = tid >> 5, lane = tid & 31;
    const int wr   = w >> 2, wc = w & 3;
    const int g    = lane >> 2, tid4 = lane & 3;

    const uint4* B1 = (const uint4*)W1img;
    const uint4* B2 = (const uint4*)W2img;

    #pragma unroll 2
    for (int i = tid; i < 2048; i += 256) {
        int r = i >> 5, c4 = i & 31, col = c4 * 4;
        float4 v = make_float4(0.f, 0.f, 0.f, 0.f);
        int gr = row0 + r;
        if (gr < M) {
            v = __ldg((const float4*)(X + (size_t)gr * 128) + c4);
            v.x = fmaf(v.x, __ldg(bnab + col + 0), __ldg(bnab + 128 + col + 0));
            v.y = fmaf(v.y, __ldg(bnab + col + 1), __ldg(bnab + 128 + col + 1));
            v.z = fmaf(v.z, __ldg(bnab + col + 2), __ldg(bnab + 128 + col + 2));
            v.w = fmaf(v.w, __ldg(bnab + col + 3), __ldg(bnab + 128 + col + 3));
        }
        split_store(Ah, Al, r * SAP + col, v);
    }
    __syncthreads();

    const uint32_t shAh = (uint32_t)__cvta_generic_to_shared(Ah);
    const uint32_t shAl = (uint32_t)__cvta_generic_to_shared(Al);
    const uint32_t shMh = (uint32_t)__cvta_generic_to_shared(Mh);
    const uint32_t shMl = (uint32_t)__cvta_generic_to_shared(Ml);
    const uint32_t aoffA = ldsm_off<SAP>(wr * 32, lane);
    const uint32_t aoffM = ldsm_off<MP>(wr * 32, lane);

    float acc1[8][2][4];
    #pragma unroll
    for (int nt = 0; nt < 8; nt++)
        #pragma unroll
        for (int mt = 0; mt < 2; mt++)
            #pragma unroll
            for (int i = 0; i < 4; i++) acc1[nt][mt][i] = 0.f;

    #pragma unroll
    for (int ks = 0; ks < 8; ks++) {
        uint32_t ah[2][4], al[2][4];
        load_afrag_ldsm<SAP>(shAh, shAl, aoffA, ks * 32, ah, al);
        #pragma unroll
        for (int ntp = 0; ntp < 4; ntp++) {
            uint4 b0 = __ldg(B1 + ((size_t)ks * 32 + (wc * 8 + ntp * 2 + 0)) * 32 + lane);
            uint4 b1 = __ldg(B1 + ((size_t)ks * 32 + (wc * 8 + ntp * 2 + 1)) * 32 + lane);
            mma_pair(acc1[ntp * 2], acc1[ntp * 2 + 1], ah, al, b0, b1);
        }
    }
    __syncthreads();

    #pragma unroll
    for (int mt = 0; mt < 2; mt++)
        #pragma unroll
        for (int half = 0; half < 2; half++) {
            int rl = wr * 32 + mt * 16 + g + half * 8;
            #pragma unroll
            for (int nt = 0; nt < 8; nt++) {
                int col = wc * 64 + nt * 8 + tid4 * 2;
                float o0 = fmaxf(acc1[nt][mt][half * 2 + 0] + __ldg(b1 + col), 0.f);
                float o1 = fmaxf(acc1[nt][mt][half * 2 + 1] + __ldg(b1 + col + 1), 0.f);
                __nv_bfloat162 h = __floats2bfloat162_rn(o0, o1);
                __nv_bfloat162 l = __floats2bfloat162_rn(o0 - __bfloat162float(h.x),
                                                         o1 - __bfloat162float(h.y));
                *(__nv_bfloat162*)(Mh + rl * MP + col) = h;
                *(__nv_bfloat162*)(Ml + rl * MP + col) = l;
            }
        }
    __syncthreads();

    float acc2[4][2][4];
    #pragma unroll
    for (int nt = 0; nt < 4; nt++)
        #pragma unroll
        for (int mt = 0; mt < 2; mt++)
            #pragma unroll
            for (int i = 0; i < 4; i++) acc2[nt][mt][i] = 0.f;

    #pragma unroll
    for (int ks = 0; ks < 16; ks++) {
        uint32_t ah[2][4], al[2][4];
        load_afrag_ldsm<MP>(shMh, shMl, aoffM, ks * 32, ah, al);
        #pragma unroll
        for (int ntp = 0; ntp < 2; ntp++) {
            uint4 b0 = __ldg(B2 + ((size_t)ks * 16 + (wc * 4 + ntp * 2 + 0)) * 32 + lane);
            uint4 b1 = __ldg(B2 + ((size_t)ks * 16 + (wc * 4 + ntp * 2 + 1)) * 32 + lane);
            mma_pair(acc2[ntp * 2], acc2[ntp * 2 + 1], ah, al, b0, b1);
        }
    }

    float s1[8], s2[8];
    #pragma unroll
    for (int j = 0; j < 8; j++) { s1[j] = 0.f; s2[j] = 0.f; }
    #pragma unroll
    for (int mt = 0; mt < 2; mt++)
        #pragma unroll
        for (int half = 0; half < 2; half++) {
            int gr = row0 + wr * 32 + mt * 16 + g + half * 8;
            if (gr >= M) continue;
            #pragma unroll
            for (int nt = 0; nt < 4; nt++) {
                int col = wc * 32 + nt * 8 + tid4 * 2;
                float o0 = acc2[nt][mt][half * 2 + 0] + __ldg(b2 + col);
                float o1 = acc2[nt][mt][half * 2 + 1] + __ldg(b2 + col + 1);
                float2 rv = __ldg((const float2*)(X + (size_t)gr * 128 + col));
                o0 = fmaf(rv.x, __ldg(bnab + col),     o0 + __ldg(bnab + 128 + col));
                o1 = fmaf(rv.y, __ldg(bnab + col + 1), o1 + __ldg(bnab + 128 + col + 1));
                s1[nt * 2 + 0] += o0; s2[nt * 2 + 0] = fmaf(o0, o0, s2[nt * 2 + 0]);
                s1[nt * 2 + 1] += o1; s2[nt * 2 + 1] = fmaf(o1, o1, s2[nt * 2 + 1]);
                *(float2*)(C + (size_t)gr * 128 + col) = make_float2(o0, o1);
            }
        }
    #pragma unroll
    for (int j = 0; j < 8; j++) {
        float a = s1[j], q = s2[j];
        a += __shfl_xor_sync(0xffffffffu, a, 4);  q += __shfl_xor_sync(0xffffffffu, q, 4);
        a += __shfl_xor_sync(0xffffffffu, a, 8);  q += __shfl_xor_sync(0xffffffffu, q, 8);
        a += __shfl_xor_sync(0xffffffffu, a, 16); q += __shfl_xor_sync(0xffffffffu, q, 16);
        if (g == 0) {
            int col = wc * 32 + (j >> 1) * 8 + tid4 * 2 + (j & 1);
            atomicAdd(stats + col, a);
            atomicAdd(stats + 128 + col, q);
        }
    }
}

// ---------------- merged finalize ----------------
__global__ void finalize_bn2(int bnA, const float* __restrict__ gA, const float* __restrict__ bA, float minvA,
                             int bnB, const float* __restrict__ gB, const float* __restrict__ bB, float minvB)
{
    int c = threadIdx.x;
    int bn; const float *g, *b; float minv;
    if (blockIdx.x == 0) { bn = bnA; g = gA; b = bA; minv = minvA; }
    else                 { bn = bnB; g = gB; b = bB; minv = minvB; }
    float mean = g_stats[bn * 2 * D + c] * minv;
    float var  = g_stats[bn * 2 * D + D + c] * minv - mean * mean;
    float rstd = rsqrtf(var + 1e-5f);
    float scv  = g[c] * rstd;
    g_bnab[bn * 2 * D + c]     = scv;
    g_bnab[bn * 2 * D + D + c] = b[c] - mean * scv;
}

// ---------------- vectorized output BN ----------------
__global__ void out_norm(float4* __restrict__ out)
{
    size_t i = (size_t)blockIdx.x * blockDim.x + threadIdx.x;
    if (i >= (size_t)(NN + NE) * 32) return;
    int c4 = (int)(i & 31) * 4;
    int bn = (i < (size_t)NN * 32) ? 2 : 3;
    const float* ab = g_bnab + bn * 2 * D;
    float4 v = out[i];
    v.x = fmaf(v.x, ab[c4 + 0], ab[128 + c4 + 0]);
    v.y = fmaf(v.y, ab[c4 + 1], ab[128 + c4 + 1]);
    v.z = fmaf(v.z, ab[c4 + 2], ab[128 + c4 + 2]);
    v.w = fmaf(v.w, ab[c4 + 3], ab[128 + c4 + 3]);
    out[i] = v;
}

// ---------------- host ----------------
extern "C" void kernel_launch(void* const* d_in, const int* in_sizes, int n_in,
                              void* d_out, int out_size)
{
    (void)in_sizes; (void)n_in; (void)out_size;
    const float* h_in  = (const float*)d_in[0];
    const float* e_in  = (const float*)d_in[1];
    const float* Wq    = (const float*)d_in[2];
    const float* Wk    = (const float*)d_in[3];
    const float* Wv    = (const float*)d_in[4];
    const float* We    = (const float*)d_in[5];
    const float* Ohw   = (const float*)d_in[6];
    const float* Ohb   = (const float*)d_in[7];
    const float* Oew   = (const float*)d_in[8];
    const float* Oeb   = (const float*)d_in[9];
    const float* bn1hg = (const float*)d_in[10];
    const float* bn1hb = (const float*)d_in[11];
    const float* bn1eg = (const float*)d_in[12];
    const float* bn1eb = (const float*)d_in[13];
    const float* fhw1  = (const float*)d_in[14];
    const float* fhb1  = (const float*)d_in[15];
    const float* fhw2  = (const float*)d_in[16];
    const float* fhb2  = (const float*)d_in[17];
    const float* few1  = (const float*)d_in[18];
    const float* feb1  = (const float*)d_in[19];
    const float* few2  = (const float*)d_in[20];
    const float* feb2  = (const float*)d_in[21];
    const float* bn2hg = (const float*)d_in[22];
    const float* bn2hb = (const float*)d_in[23];
    const float* bn2eg = (const float*)d_in[24];
    const float* bn2eb = (const float*)d_in[25];
    const int*   src   = (const int*)d_in[26];
    const int*   dst   = (const int*)d_in[27];

    float* out  = (float*)d_out;
    float* outh = out;
    float* oute = out + (size_t)NN * D;

    float *pQ, *pK, *pV, *pwV, *pz, *ph2, *pe2, *pstats, *pbnab;
    __nv_bfloat16* pimg;
    cudaGetSymbolAddress((void**)&pQ,    g_Q);
    cudaGetSymbolAddress((void**)&pK,    g_Kb);
    cudaGetSymbolAddress((void**)&pV,    g_V);
    cudaGetSymbolAddress((void**)&pwV,   g_wV);
    cudaGetSymbolAddress((void**)&pz,    g_z);
    cudaGetSymbolAddress((void**)&ph2,   g_h2);
    cudaGetSymbolAddress((void**)&pe2,   g_e2);
    cudaGetSymbolAddress((void**)&pstats, g_stats);
    cudaGetSymbolAddress((void**)&pbnab,  g_bnab);
    cudaGetSymbolAddress((void**)&pimg,   g_wimg);

    const size_t oWe = 0, oWq = 32768, oWk = 65536, oWv = 98304;
    const size_t oOh = 131072, oOe = 163840;
    const size_t oF1h = 196608, oF1e = 262144, oF2h = 327680, oF2e = 393216;

    auto kBh = mm_k<1, 1, 1, 1>;

    const int SMEM_64 = 2 * 64 * 136 * 2;    // 34816
    const int SMEM_E  = 4 * 64 * 136 * 2;    // 69632
    const int SMEM_F  = 2 * 64 * 264 * 2;    // 67584
    cudaFuncSetAttribute(kBh,   cudaFuncAttributeMaxDynamicSharedMemorySize, SMEM_64);
    cudaFuncSetAttribute(qkv_k, cudaFuncAttributeMaxDynamicSharedMemorySize, SMEM_64);
    cudaFuncSetAttribute(epj_k, cudaFuncAttributeMaxDynamicSharedMemorySize, SMEM_E);
    cudaFuncSetAttribute(ffn_k, cudaFuncAttributeMaxDynamicSharedMemorySize, SMEM_F);

    const int gN64 = (NN + 63) / 64;
    const int gE64 = (NE + 63) / 64;

    cudaMemsetAsync(pwV,    0, sizeof(float) * NN * D);
    cudaMemsetAsync(pz,     0, sizeof(float) * NN * 8);
    cudaMemsetAsync(pstats, 0, sizeof(float) * 4 * 2 * D);

    PrepArgs pa;
    pa.src[0] = We;   pa.src[1] = Wq;   pa.src[2] = Wk;   pa.src[3] = Wv;
    pa.src[4] = Ohw;  pa.src[5] = Oew;
    pa.src[6] = fhw1; pa.src[7] = few1; pa.src[8] = fhw2; pa.src[9] = few2;
    prep_all<<<(229376 + 255) / 256, 256>>>(pa, pimg);

    qkv_k<<<dim3(1, gN64), 256, SMEM_64>>>(h_in, pimg + oWq, pimg + oWk, pimg + oWv, pQ, pK, pV, NN);

    epj_k<<<gE64, 256, SMEM_E>>>(e_in, pimg + oWe, pimg + oOe, Oeb, src, dst,
                                 pstats + 1 * 2 * D, pe2, NE);

    kBh<<<dim3(1, gN64), 256, SMEM_64>>>(pwV, pimg + oOh, Ohb, h_in, nullptr, pz,
                                         pstats + 0 * 2 * D, ph2, NN);

    finalize_bn2<<<2, D>>>(0, bn1hg, bn1hb, 1.f / NN, 1, bn1eg, bn1eb, 1.f / NE);

    ffn_k<<<gN64 + gE64, 256, SMEM_F>>>(ph2, pe2,
                                        pimg + oF1h, pimg + oF1e, fhb1, feb1,
                                        pimg + oF2h, pimg + oF2e, fhb2, feb2,
                                        pbnab + 0 * 2 * D, pbnab + 1 * 2 * D,
                                        pstats + 2 * 2 * D, pstats + 3 * 2 * D,
                                        outh, oute, gN64);

    finalize_bn2<<<2, D>>>(2, bn2hg, bn2hb, 1.f / NN, 3, bn2eg, bn2eb, 1.f / NE);

    out_norm<<<(int)(((size_t)(NN + NE) * 32 + 255) / 256), 256>>>((float4*)out);
}

// round 17
// speedup vs baseline: 1.0762x; 1.0034x over previous
#include <cuda_runtime.h>
#include <cuda_bf16.h>
#include <math.h>
#include <stdint.h>

#define NN 50000
#define NE 800000
#define D  128

// ---------------- scratch ----------------
static __device__ float g_Q  [NN * D];
static __device__ float g_Kb [NN * D];
static __device__ float g_V  [NN * D];
static __device__ float g_wV [NN * D];
static __device__ float g_z  [NN * 8];
static __device__ float g_h2 [NN * D];
static __device__ float g_e2 [(size_t)NE * D];
static __device__ float g_stats[4 * 2 * D];
static __device__ float g_bnab [4 * 2 * D];
static __device__ __nv_bfloat16 g_wimg[458752];

// ---------------- merged weight prep ----------------
struct PrepArgs { const float* src[10]; };

__global__ void prep_all(PrepArgs args, __nv_bfloat16* __restrict__ img)
{
    int idx = blockIdx.x * blockDim.x + threadIdx.x;
    if (idx >= 229376) return;
    int w, off, K, N;
    size_t ooff;
    if (idx < 98304) {
        w = idx >> 14; off = idx & 16383; K = 128; N = 128;
        ooff = (size_t)w * 32768;
    } else {
        int t = idx - 98304;
        w = 6 + (t >> 15); off = t & 32767;
        if (w < 8) { K = 128; N = 256; } else { K = 256; N = 128; }
        ooff = 196608 + (size_t)(w - 6) * 65536;
    }
    const float* W = args.src[w];
    int k = off / N, n = off - k * N;
    float wv = __ldg(W + off);
    __nv_bfloat16 hi = __float2bfloat16(wv);
    __nv_bfloat16 lo = __float2bfloat16(wv - __bfloat162float(hi));
    int kstep = k >> 4, kin = k & 15;
    int reg  = (kin >> 3) & 1;
    int tid4 = (kin >> 1) & 3;
    int p    = kin & 1;
    int gg   = n & 7;
    int ntile = n >> 3;
    int lane = gg * 4 + tid4;
    size_t idx4 = ((size_t)kstep * (N >> 3) + ntile) * 32 + lane;
    img[ooff + idx4 * 8 + reg * 2 + p]     = hi;
    img[ooff + idx4 * 8 + 4 + reg * 2 + p] = lo;
}

__device__ __forceinline__ void mma16816(float* c, const uint32_t* a, uint32_t b0, uint32_t b1)
{
    asm volatile(
        "mma.sync.aligned.m16n8k16.row.col.f32.bf16.bf16.f32 "
        "{%0,%1,%2,%3}, {%4,%5,%6,%7}, {%8,%9}, {%0,%1,%2,%3};"
        : "+f"(c[0]), "+f"(c[1]), "+f"(c[2]), "+f"(c[3])
        : "r"(a[0]), "r"(a[1]), "r"(a[2]), "r"(a[3]), "r"(b0), "r"(b1));
}

__device__ __forceinline__ void ldsm4(uint32_t r[4], uint32_t addr)
{
    asm volatile("ldmatrix.sync.aligned.m8n8.x4.shared.b16 {%0,%1,%2,%3}, [%4];"
                 : "=r"(r[0]), "=r"(r[1]), "=r"(r[2]), "=r"(r[3]) : "r"(addr));
}

template<int STRIDE>
__device__ __forceinline__ uint32_t ldsm_off(int r0, int lane)
{
    int row = r0 + (lane & 7) + ((lane >> 3) & 1) * 8;
    int col = ((lane >> 4) & 1) * 8;
    return (uint32_t)((row * STRIDE + col) * 2);
}

template<int STRIDE>
__device__ __forceinline__ void load_afrag_ldsm(uint32_t shH, uint32_t shL, uint32_t aoff,
                                                uint32_t ksbyte, uint32_t ah[2][4], uint32_t al[2][4])
{
    ldsm4(ah[0], shH + aoff + ksbyte);
    ldsm4(ah[1], shH + aoff + ksbyte + 16 * STRIDE * 2);
    ldsm4(al[0], shL + aoff + ksbyte);
    ldsm4(al[1], shL + aoff + ksbyte + 16 * STRIDE * 2);
}

__device__ __forceinline__ void split_store(__nv_bfloat16* Ah, __nv_bfloat16* Al,
                                            int off, float4 v)
{
    __nv_bfloat162 h0 = __floats2bfloat162_rn(v.x, v.y);
    __nv_bfloat162 h1 = __floats2bfloat162_rn(v.z, v.w);
    __nv_bfloat162 l0 = __floats2bfloat162_rn(v.x - __bfloat162float(h0.x),
                                              v.y - __bfloat162float(h0.y));
    __nv_bfloat162 l1 = __floats2bfloat162_rn(v.z - __bfloat162float(h1.x),
                                              v.w - __bfloat162float(h1.y));
    *(__nv_bfloat162*)(Ah + off)     = h0;
    *(__nv_bfloat162*)(Ah + off + 2) = h1;
    *(__nv_bfloat162*)(Al + off)     = l0;
    *(__nv_bfloat162*)(Al + off + 2) = l1;
}

__device__ __forceinline__ void mma_pair(float acc0[2][4], float acc1[2][4],
                                         const uint32_t ah[2][4], const uint32_t al[2][4],
                                         uint4 b0, uint4 b1)
{
    mma16816(acc0[0], ah[0], b0.x, b0.y);
    mma16816(acc0[1], ah[1], b0.x, b0.y);
    mma16816(acc1[0], ah[0], b1.x, b1.y);
    mma16816(acc1[1], ah[1], b1.x, b1.y);
    mma16816(acc0[0], ah[0], b0.z, b0.w);
    mma16816(acc0[1], ah[1], b0.z, b0.w);
    mma16816(acc1[0], ah[0], b1.z, b1.w);
    mma16816(acc1[1], ah[1], b1.z, b1.w);
    mma16816(acc0[0], al[0], b0.x, b0.y);
    mma16816(acc0[1], al[1], b0.x, b0.y);
    mma16816(acc1[0], al[0], b1.x, b1.y);
    mma16816(acc1[1], al[1], b1.x, b1.y);
}

// ---------------- h-side O-proj GEMM, 64-row tiles, 3 CTA/SM ----------------
template<int BIAS, int RESM, int DO_STATS, int DIVZ>
__global__ void __launch_bounds__(256, 3)
mm_k(const float* __restrict__ X, const __nv_bfloat16* __restrict__ Wimg,
     const float* __restrict__ bias, const float* __restrict__ res,
     const float* __restrict__ res_ab,
     const float* __restrict__ zdiv, float* __restrict__ stats,
     float* __restrict__ C, int M)
{
    constexpr int SAP = 136;
    extern __shared__ __nv_bfloat16 sA[];
    __nv_bfloat16* Ah = sA;
    __nv_bfloat16* Al = sA + 64 * SAP;

    const int tid  = threadIdx.x;
    const int w    = tid >> 5, lane = tid & 31;
    const int wr   = w >> 2, wc = w & 3;
    const int g    = lane >> 2, tid4 = lane & 3;
    const int row0 = blockIdx.y * 64;

    const uint4* Bimg = (const uint4*)Wimg;

    float acc[4][2][4];
    #pragma unroll
    for (int nt = 0; nt < 4; nt++)
        #pragma unroll
        for (int mt = 0; mt < 2; mt++)
            #pragma unroll
            for (int i = 0; i < 4; i++) acc[nt][mt][i] = 0.f;

    #pragma unroll 2
    for (int i = tid; i < 2048; i += 256) {
        int r = i >> 5, c4 = i & 31, col = c4 * 4;
        float4 v = make_float4(0.f, 0.f, 0.f, 0.f);
        int gr = row0 + r;
        if (gr < M) {
            v = __ldg((const float4*)(X + (size_t)gr * 128) + c4);
            if (DIVZ) {
                float inv = 1.0f / (__ldg(zdiv + gr * 8 + (c4 >> 2)) + 1e-6f);
                v.x *= inv; v.y *= inv; v.z *= inv; v.w *= inv;
            }
        }
        split_store(Ah, Al, r * SAP + col, v);
    }
    __syncthreads();

    const uint32_t shAh = (uint32_t)__cvta_generic_to_shared(Ah);
    const uint32_t shAl = (uint32_t)__cvta_generic_to_shared(Al);
    const uint32_t aoff = ldsm_off<SAP>(wr * 32, lane);

    #pragma unroll
    for (int ks = 0; ks < 8; ks++) {
        uint32_t ah[2][4], al[2][4];
        load_afrag_ldsm<SAP>(shAh, shAl, aoff, ks * 32, ah, al);
        #pragma unroll
        for (int ntp = 0; ntp < 2; ntp++) {
            uint4 b0 = __ldg(Bimg + ((size_t)ks * 16 + (wc * 4 + ntp * 2 + 0)) * 32 + lane);
            uint4 b1 = __ldg(Bimg + ((size_t)ks * 16 + (wc * 4 + ntp * 2 + 1)) * 32 + lane);
            mma_pair(acc[ntp * 2], acc[ntp * 2 + 1], ah, al, b0, b1);
        }
    }

    float s1[8], s2[8];
    if (DO_STATS) {
        #pragma unroll
        for (int j = 0; j < 8; j++) { s1[j] = 0.f; s2[j] = 0.f; }
    }
    #pragma unroll
    for (int mt = 0; mt < 2; mt++)
        #pragma unroll
        for (int half = 0; half < 2; half++) {
            int gr = row0 + wr * 32 + mt * 16 + g + half * 8;
            if (gr >= M) continue;
            #pragma unroll
            for (int nt = 0; nt < 4; nt++) {
                int col = wc * 32 + nt * 8 + tid4 * 2;
                float o0 = acc[nt][mt][half * 2 + 0];
                float o1 = acc[nt][mt][half * 2 + 1];
                if (BIAS) { o0 += __ldg(bias + col); o1 += __ldg(bias + col + 1); }
                if (RESM) {
                    float2 rv = __ldg((const float2*)(res + (size_t)gr * D + col));
                    o0 += rv.x; o1 += rv.y;
                }
                if (DO_STATS) {
                    s1[nt * 2 + 0] += o0; s2[nt * 2 + 0] = fmaf(o0, o0, s2[nt * 2 + 0]);
                    s1[nt * 2 + 1] += o1; s2[nt * 2 + 1] = fmaf(o1, o1, s2[nt * 2 + 1]);
                }
                *(float2*)(C + (size_t)gr * D + col) = make_float2(o0, o1);
            }
        }
    if (DO_STATS) {
        #pragma unroll
        for (int j = 0; j < 8; j++) {
            float a = s1[j], q = s2[j];
            a += __shfl_xor_sync(0xffffffffu, a, 4);  q += __shfl_xor_sync(0xffffffffu, q, 4);
            a += __shfl_xor_sync(0xffffffffu, a, 8);  q += __shfl_xor_sync(0xffffffffu, q, 8);
            a += __shfl_xor_sync(0xffffffffu, a, 16); q += __shfl_xor_sync(0xffffffffu, q, 16);
            if (g == 0) {
                int col = wc * 32 + (j >> 1) * 8 + tid4 * 2 + (j & 1);
                atomicAdd(stats + col, a);
                atomicAdd(stats + 128 + col, q);
            }
        }
    }
}

// ---------------- fused QKV, 64-row tiles, 3 CTA/SM ----------------
__global__ void __launch_bounds__(256, 3)
qkv_k(const float* __restrict__ X,
      const __nv_bfloat16* __restrict__ Wq, const __nv_bfloat16* __restrict__ Wk,
      const __nv_bfloat16* __restrict__ Wv,
      float* __restrict__ Cq, float* __restrict__ Ck, float* __restrict__ Cv, int M)
{
    constexpr int SAP = 136;
    extern __shared__ __nv_bfloat16 sA[];
    __nv_bfloat16* Ah = sA;
    __nv_bfloat16* Al = sA + 64 * SAP;

    const int tid  = threadIdx.x;
    const int w    = tid >> 5, lane = tid & 31;
    const int wr   = w >> 2, wc = w & 3;
    const int g    = lane >> 2, tid4 = lane & 3;
    const int row0 = blockIdx.y * 64;

    #pragma unroll 2
    for (int i = tid; i < 2048; i += 256) {
        int r = i >> 5, c4 = i & 31, col = c4 * 4;
        float4 v = make_float4(0.f, 0.f, 0.f, 0.f);
        int gr = row0 + r;
        if (gr < M) v = __ldg((const float4*)(X + (size_t)gr * 128) + c4);
        split_store(Ah, Al, r * SAP + col, v);
    }
    __syncthreads();

    const uint32_t shAh = (uint32_t)__cvta_generic_to_shared(Ah);
    const uint32_t shAl = (uint32_t)__cvta_generic_to_shared(Al);
    const uint32_t aoff = ldsm_off<SAP>(wr * 32, lane);

    const __nv_bfloat16* Ws[3] = {Wq, Wk, Wv};
    float* Cs[3] = {Cq, Ck, Cv};
    #pragma unroll 1
    for (int wsel = 0; wsel < 3; wsel++) {
        const uint4* Bimg = (const uint4*)Ws[wsel];
        float* C = Cs[wsel];
        float acc[4][2][4];
        #pragma unroll
        for (int nt = 0; nt < 4; nt++)
            #pragma unroll
            for (int mt = 0; mt < 2; mt++)
                #pragma unroll
                for (int i = 0; i < 4; i++) acc[nt][mt][i] = 0.f;
        #pragma unroll
        for (int ks = 0; ks < 8; ks++) {
            uint32_t ah[2][4], al[2][4];
            load_afrag_ldsm<SAP>(shAh, shAl, aoff, ks * 32, ah, al);
            #pragma unroll
            for (int ntp = 0; ntp < 2; ntp++) {
                uint4 b0 = __ldg(Bimg + ((size_t)ks * 16 + (wc * 4 + ntp * 2 + 0)) * 32 + lane);
                uint4 b1 = __ldg(Bimg + ((size_t)ks * 16 + (wc * 4 + ntp * 2 + 1)) * 32 + lane);
                mma_pair(acc[ntp * 2], acc[ntp * 2 + 1], ah, al, b0, b1);
            }
        }
        #pragma unroll
        for (int mt = 0; mt < 2; mt++)
            #pragma unroll
            for (int half = 0; half < 2; half++) {
                int gr = row0 + wr * 32 + mt * 16 + g + half * 8;
                if (gr >= M) continue;
                #pragma unroll
                for (int nt = 0; nt < 4; nt++) {
                    int col = wc * 32 + nt * 8 + tid4 * 2;
                    *(float2*)(C + (size_t)gr * D + col) =
                        make_float2(acc[nt][mt][half * 2 + 0], acc[nt][mt][half * 2 + 1]);
                }
            }
    }
}

// ---------------- fused edge pipeline, 3 CTA/SM (slim edge phase) ----------------
__global__ void __launch_bounds__(256, 3)
epj_k(const float* __restrict__ X, const __nv_bfloat16* __restrict__ W1img,
      const __nv_bfloat16* __restrict__ W2img, const float* __restrict__ bias,
      const int* __restrict__ src, const int* __restrict__ dst,
      float* __restrict__ stats, float* __restrict__ C, int M)
{
    constexpr int SAP = 136;
    extern __shared__ __nv_bfloat16 sm[];
    __nv_bfloat16* Ah = sm;
    __nv_bfloat16* Al = sm + 64 * SAP;
    __nv_bfloat16* Sh = sm + 2 * 64 * SAP;
    __nv_bfloat16* Sl = sm + 3 * 64 * SAP;

    const int tid  = threadIdx.x;
    const int w    = tid >> 5, lane = tid & 31;
    const int wr   = w >> 2, wc = w & 3;
    const int g    = lane >> 2, tid4 = lane & 3;
    const int row0 = blockIdx.x * 64;

    const uint4* B1 = (const uint4*)W1img;
    const uint4* B2 = (const uint4*)W2img;

    #pragma unroll 2
    for (int i = tid; i < 2048; i += 256) {
        int r = i >> 5, c4 = i & 31, col = c4 * 4;
        float4 v = make_float4(0.f, 0.f, 0.f, 0.f);
        int gr = row0 + r;
        if (gr < M) v = __ldg((const float4*)(X + (size_t)gr * 128) + c4);
        split_store(Ah, Al, r * SAP + col, v);
    }
    __syncthreads();

    const uint32_t shAh = (uint32_t)__cvta_generic_to_shared(Ah);
    const uint32_t shAl = (uint32_t)__cvta_generic_to_shared(Al);
    const uint32_t shSh = (uint32_t)__cvta_generic_to_shared(Sh);
    const uint32_t shSl = (uint32_t)__cvta_generic_to_shared(Sl);
    const uint32_t aoff = ldsm_off<SAP>(wr * 32, lane);

    float acc1[4][2][4];
    #pragma unroll
    for (int nt = 0; nt < 4; nt++)
        #pragma unroll
        for (int mt = 0; mt < 2; mt++)
            #pragma unroll
            for (int i = 0; i < 4; i++) acc1[nt][mt][i] = 0.f;
    #pragma unroll
    for (int ks = 0; ks < 8; ks++) {
        uint32_t ah[2][4], al[2][4];
        load_afrag_ldsm<SAP>(shAh, shAl, aoff, ks * 32, ah, al);
        #pragma unroll
        for (int ntp = 0; ntp < 2; ntp++) {
            uint4 b0 = __ldg(B1 + ((size_t)ks * 16 + (wc * 4 + ntp * 2 + 0)) * 32 + lane);
            uint4 b1 = __ldg(B1 + ((size_t)ks * 16 + (wc * 4 + ntp * 2 + 1)) * 32 + lane);
            mma_pair(acc1[ntp * 2], acc1[ntp * 2 + 1], ah, al, b0, b1);
        }
    }
    #pragma unroll
    for (int mt = 0; mt < 2; mt++)
        #pragma unroll
        for (int half = 0; half < 2; half++) {
            int rl = wr * 32 + mt * 16 + g + half * 8;
            #pragma unroll
            for (int nt = 0; nt < 4; nt++) {
                int col = wc * 32 + nt * 8 + tid4 * 2;
                float o0 = acc1[nt][mt][half * 2 + 0];
                float o1 = acc1[nt][mt][half * 2 + 1];
                __nv_bfloat162 h = __floats2bfloat162_rn(o0, o1);
                __nv_bfloat162 l = __floats2bfloat162_rn(o0 - __bfloat162float(h.x),
                                                         o1 - __bfloat162float(h.y));
                *(__nv_bfloat162*)(Sh + rl * SAP + col) = h;
                *(__nv_bfloat162*)(Sl + rl * SAP + col) = l;
            }
        }
    __syncthreads();

    // edge phase: src/dst loaded in-loop (register-slim), unroll 2 for MLP
    #pragma unroll 2
    for (int i = 0; i < 8; i++) {
        int rl = w * 8 + i;
        int er = row0 + rl;
        int s = __ldg(src + er), d = __ldg(dst + er);
        __nv_bfloat162 h0 = *(__nv_bfloat162*)(Sh + rl * SAP + lane * 4);
        __nv_bfloat162 h1 = *(__nv_bfloat162*)(Sh + rl * SAP + lane * 4 + 2);
        __nv_bfloat162 l0 = *(__nv_bfloat162*)(Sl + rl * SAP + lane * 4);
        __nv_bfloat162 l1 = *(__nv_bfloat162*)(Sl + rl * SAP + lane * 4 + 2);
        float4 p;
        p.x = __bfloat162float(h0.x) + __bfloat162float(l0.x);
        p.y = __bfloat162float(h0.y) + __bfloat162float(l0.y);
        p.z = __bfloat162float(h1.x) + __bfloat162float(l1.x);
        p.w = __bfloat162float(h1.y) + __bfloat162float(l1.y);
        float4 q = __ldg((const float4*)(g_Q  + (size_t)d * D) + lane);
        float4 k = __ldg((const float4*)(g_Kb + (size_t)s * D) + lane);
        float4 sc;
        sc.x = k.x * q.x * 0.25f * p.x;
        sc.y = k.y * q.y * 0.25f * p.y;
        sc.z = k.z * q.z * 0.25f * p.z;
        sc.w = k.w * q.w * 0.25f * p.w;
        split_store(Sh, Sl, rl * SAP + lane * 4, sc);
        float part = sc.x + sc.y + sc.z + sc.w;
        part += __shfl_xor_sync(0xffffffffu, part, 1);
        part += __shfl_xor_sync(0xffffffffu, part, 2);
        part  = fminf(fmaxf(part, -5.f), 5.f);
        float sh = expf(part);
        float4 v = __ldg((const float4*)(g_V + (size_t)s * D) + lane);
        float* wv = g_wV + (size_t)d * D + lane * 4;
        asm volatile("red.global.add.v4.f32 [%0], {%1, %2, %3, %4};"
                     :: "l"(wv), "f"(v.x * sh), "f"(v.y * sh), "f"(v.z * sh), "f"(v.w * sh)
                     : "memory");
        if ((lane & 3) == 0) atomicAdd(g_z + (size_t)d * 8 + (lane >> 2), sh);
    }
    __syncthreads();

    float acc2[4][2][4];
    #pragma unroll
    for (int nt = 0; nt < 4; nt++)
        #pragma unroll
        for (int mt = 0; mt < 2; mt++)
            #pragma unroll
            for (int i = 0; i < 4; i++) acc2[nt][mt][i] = 0.f;
    #pragma unroll
    for (int ks = 0; ks < 8; ks++) {
        uint32_t ah[2][4], al[2][4];
        load_afrag_ldsm<SAP>(shSh, shSl, aoff, ks * 32, ah, al);
        #pragma unroll
        for (int ntp = 0; ntp < 2; ntp++) {
            uint4 b0 = __ldg(B2 + ((size_t)ks * 16 + (wc * 4 + ntp * 2 + 0)) * 32 + lane);
            uint4 b1 = __ldg(B2 + ((size_t)ks * 16 + (wc * 4 + ntp * 2 + 1)) * 32 + lane);
            mma_pair(acc2[ntp * 2], acc2[ntp * 2 + 1], ah, al, b0, b1);
        }
    }

    float s1[8], s2[8];
    #pragma unroll
    for (int j = 0; j < 8; j++) { s1[j] = 0.f; s2[j] = 0.f; }
    #pragma unroll
    for (int mt = 0; mt < 2; mt++)
        #pragma unroll
        for (int half = 0; half < 2; half++) {
            int rl = wr * 32 + mt * 16 + g + half * 8;
            int gr = row0 + rl;
            if (gr >= M) continue;
            #pragma unroll
            for (int nt = 0; nt < 4; nt++) {
                int col = wc * 32 + nt * 8 + tid4 * 2;
                float o0 = acc2[nt][mt][half * 2 + 0] + __ldg(bias + col);
                float o1 = acc2[nt][mt][half * 2 + 1] + __ldg(bias + col + 1);
                __nv_bfloat162 rh  = *(__nv_bfloat162*)(Ah + rl * SAP + col);
                __nv_bfloat162 rlo = *(__nv_bfloat162*)(Al + rl * SAP + col);
                o0 += __bfloat162float(rh.x) + __bfloat162float(rlo.x);
                o1 += __bfloat162float(rh.y) + __bfloat162float(rlo.y);
                s1[nt * 2 + 0] += o0; s2[nt * 2 + 0] = fmaf(o0, o0, s2[nt * 2 + 0]);
                s1[nt * 2 + 1] += o1; s2[nt * 2 + 1] = fmaf(o1, o1, s2[nt * 2 + 1]);
                *(float2*)(C + (size_t)gr * 128 + col) = make_float2(o0, o1);
            }
        }
    #pragma unroll
    for (int j = 0; j < 8; j++) {
        float a = s1[j], q = s2[j];
        a += __shfl_xor_sync(0xffffffffu, a, 4);  q += __shfl_xor_sync(0xffffffffu, q, 4);
        a += __shfl_xor_sync(0xffffffffu, a, 8);  q += __shfl_xor_sync(0xffffffffu, q, 8);
        a += __shfl_xor_sync(0xffffffffu, a, 16); q += __shfl_xor_sync(0xffffffffu, q, 16);
        if (g == 0) {
            int col = wc * 32 + (j >> 1) * 8 + tid4 * 2 + (j & 1);
            atomicAdd(stats + col, a);
            atomicAdd(stats + 128 + col, q);
        }
    }
}

// ---------------- combined fused FFN (2 CTA/SM) ----------------
__global__ void __launch_bounds__(256, 2)
ffn_k(const float* __restrict__ Xh, const float* __restrict__ Xe,
      const __nv_bfloat16* __restrict__ W1h, const __nv_bfloat16* __restrict__ W1e,
      const float* __restrict__ b1h, const float* __restrict__ b1e,
      const __nv_bfloat16* __restrict__ W2h, const __nv_bfloat16* __restrict__ W2e,
      const float* __restrict__ b2h, const float* __restrict__ b2e,
      const float* __restrict__ bnab_h, const float* __restrict__ bnab_e,
      float* __restrict__ stats_h, float* __restrict__ stats_e,
      float* __restrict__ Ch, float* __restrict__ Ce, int gNh)
{
    constexpr int SAP = 136, MP = 264;
    extern __shared__ __nv_bfloat16 sm[];
    __nv_bfloat16* Ah = sm;
    __nv_bfloat16* Al = sm + 64 * SAP;
    __nv_bfloat16* Mh = sm;
    __nv_bfloat16* Ml = sm + 64 * MP;

    const int bid = blockIdx.x;
    const float* X; const __nv_bfloat16 *W1img, *W2img;
    const float *b1, *b2, *bnab; float *stats, *C;
    int M, row0;
    if (bid < gNh) {
        X = Xh; W1img = W1h; W2img = W2h; b1 = b1h; b2 = b2h;
        bnab = bnab_h; stats = stats_h; C = Ch; M = NN; row0 = bid * 64;
    } else {
        X = Xe; W1img = W1e; W2img = W2e; b1 = b1e; b2 = b2e;
        bnab = bnab_e; stats = stats_e; C = Ce; M = NE; row0 = (bid - gNh) * 64;
    }

    const int tid  = threadIdx.x;
    const int w    = tid >> 5, lane = tid & 31;
    const int wr   = w >> 2, wc = w & 3;
    const int g    = lane >> 2, tid4 = lane & 3;

    const uint4* B1 = (const uint4*)W1img;
    const uint4* B2 = (const uint4*)W2img;

    #pragma unroll 2
    for (int i = tid; i < 2048; i += 256) {
        int r = i >> 5, c4 = i & 31, col = c4 * 4;
        float4 v = make_float4(0.f, 0.f, 0.f, 0.f);
        int gr = row0 + r;
        if (gr < M) {
            v = __ldg((const float4*)(X + (size_t)gr * 128) + c4);
            v.x = fmaf(v.x, __ldg(bnab + col + 0), __ldg(bnab + 128 + col + 0));
            v.y = fmaf(v.y, __ldg(bnab + col + 1), __ldg(bnab + 128 + col + 1));
            v.z = fmaf(v.z, __ldg(bnab + col + 2), __ldg(bnab + 128 + col + 2));
            v.w = fmaf(v.w, __ldg(bnab + col + 3), __ldg(bnab + 128 + col + 3));
        }
        split_store(Ah, Al, r * SAP + col, v);
    }
    __syncthreads();

    const uint32_t shAh = (uint32_t)__cvta_generic_to_shared(Ah);
    const uint32_t shAl = (uint32_t)__cvta_generic_to_shared(Al);
    const uint32_t shMh = (uint32_t)__cvta_generic_to_shared(Mh);
    const uint32_t shMl = (uint32_t)__cvta_generic_to_shared(Ml);
    const uint32_t aoffA = ldsm_off<SAP>(wr * 32, lane);
    const uint32_t aoffM = ldsm_off<MP>(wr * 32, lane);

    float acc1[8][2][4];
    #pragma unroll
    for (int nt = 0; nt < 8; nt++)
        #pragma unroll
        for (int mt = 0; mt < 2; mt++)
            #pragma unroll
            for (int i = 0; i < 4; i++) acc1[nt][mt][i] = 0.f;

    #pragma unroll
    for (int ks = 0; ks < 8; ks++) {
        uint32_t ah[2][4], al[2][4];
        load_afrag_ldsm<SAP>(shAh, shAl, aoffA, ks * 32, ah, al);
        #pragma unroll
        for (int ntp = 0; ntp < 4; ntp++) {
            uint4 b0 = __ldg(B1 + ((size_t)ks * 32 + (wc * 8 + ntp * 2 + 0)) * 32 + lane);
            uint4 b1 = __ldg(B1 + ((size_t)ks * 32 + (wc * 8 + ntp * 2 + 1)) * 32 + lane);
            mma_pair(acc1[ntp * 2], acc1[ntp * 2 + 1], ah, al, b0, b1);
        }
    }
    __syncthreads();

    #pragma unroll
    for (int mt = 0; mt < 2; mt++)
        #pragma unroll
        for (int half = 0; half < 2; half++) {
            int rl = wr * 32 + mt * 16 + g + half * 8;
            #pragma unroll
            for (int nt = 0; nt < 8; nt++) {
                int col = wc * 64 + nt * 8 + tid4 * 2;
                float o0 = fmaxf(acc1[nt][mt][half * 2 + 0] + __ldg(b1 + col), 0.f);
                float o1 = fmaxf(acc1[nt][mt][half * 2 + 1] + __ldg(b1 + col + 1), 0.f);
                __nv_bfloat162 h = __floats2bfloat162_rn(o0, o1);
                __nv_bfloat162 l = __floats2bfloat162_rn(o0 - __bfloat162float(h.x),
                                                         o1 - __bfloat162float(h.y));
                *(__nv_bfloat162*)(Mh + rl * MP + col) = h;
                *(__nv_bfloat162*)(Ml + rl * MP + col) = l;
            }
        }
    __syncthreads();

    float acc2[4][2][4];
    #pragma unroll
    for (int nt = 0; nt < 4; nt++)
        #pragma unroll
        for (int mt = 0; mt < 2; mt++)
            #pragma unroll
            for (int i = 0; i < 4; i++) acc2[nt][mt][i] = 0.f;

    #pragma unroll
    for (int ks = 0; ks < 16; ks++) {
        uint32_t ah[2][4], al[2][4];
        load_afrag_ldsm<MP>(shMh, shMl, aoffM, ks * 32, ah, al);
        #pragma unroll
        for (int ntp = 0; ntp < 2; ntp++) {
            uint4 b0 = __ldg(B2 + ((size_t)ks * 16 + (wc * 4 + ntp * 2 + 0)) * 32 + lane);
            uint4 b1 = __ldg(B2 + ((size_t)ks * 16 + (wc * 4 + ntp * 2 + 1)) * 32 + lane);
            mma_pair(acc2[ntp * 2], acc2[ntp * 2 + 1], ah, al, b0, b1);
        }
    }

    float s1[8], s2[8];
    #pragma unroll
    for (int j = 0; j < 8; j++) { s1[j] = 0.f; s2[j] = 0.f; }
    #pragma unroll
    for (int mt = 0; mt < 2; mt++)
        #pragma unroll
        for (int half = 0; half < 2; half++) {
            int gr = row0 + wr * 32 + mt * 16 + g + half * 8;
            if (gr >= M) continue;
            #pragma unroll
            for (int nt = 0; nt < 4; nt++) {
                int col = wc * 32 + nt * 8 + tid4 * 2;
                float o0 = acc2[nt][mt][half * 2 + 0] + __ldg(b2 + col);
                float o1 = acc2[nt][mt][half * 2 + 1] + __ldg(b2 + col + 1);
                float2 rv = __ldg((const float2*)(X + (size_t)gr * 128 + col));
                o0 = fmaf(rv.x, __ldg(bnab + col),     o0 + __ldg(bnab + 128 + col));
                o1 = fmaf(rv.y, __ldg(bnab + col + 1), o1 + __ldg(bnab + 128 + col + 1));
                s1[nt * 2 + 0] += o0; s2[nt * 2 + 0] = fmaf(o0, o0, s2[nt * 2 + 0]);
                s1[nt * 2 + 1] += o1; s2[nt * 2 + 1] = fmaf(o1, o1, s2[nt * 2 + 1]);
                *(float2*)(C + (size_t)gr * 128 + col) = make_float2(o0, o1);
            }
        }
    #pragma unroll
    for (int j = 0; j < 8; j++) {
        float a = s1[j], q = s2[j];
        a += __shfl_xor_sync(0xffffffffu, a, 4);  q += __shfl_xor_sync(0xffffffffu, q, 4);
        a += __shfl_xor_sync(0xffffffffu, a, 8);  q += __shfl_xor_sync(0xffffffffu, q, 8);
        a += __shfl_xor_sync(0xffffffffu, a, 16); q += __shfl_xor_sync(0xffffffffu, q, 16);
        if (g == 0) {
            int col = wc * 32 + (j >> 1) * 8 + tid4 * 2 + (j & 1);
            atomicAdd(stats + col, a);
            atomicAdd(stats + 128 + col, q);
        }
    }
}

// ---------------- merged finalize ----------------
__global__ void finalize_bn2(int bnA, const float* __restrict__ gA, const float* __restrict__ bA, float minvA,
                             int bnB, const float* __restrict__ gB, const float* __restrict__ bB, float minvB)
{
    int c = threadIdx.x;
    int bn; const float *g, *b; float minv;
    if (blockIdx.x == 0) { bn = bnA; g = gA; b = bA; minv = minvA; }
    else                 { bn = bnB; g = gB; b = bB; minv = minvB; }
    float mean = g_stats[bn * 2 * D + c] * minv;
    float var  = g_stats[bn * 2 * D + D + c] * minv - mean * mean;
    float rstd = rsqrtf(var + 1e-5f);
    float scv  = g[c] * rstd;
    g_bnab[bn * 2 * D + c]     = scv;
    g_bnab[bn * 2 * D + D + c] = b[c] - mean * scv;
}

// ---------------- vectorized output BN ----------------
__global__ void out_norm(float4* __restrict__ out)
{
    size_t i = (size_t)blockIdx.x * blockDim.x + threadIdx.x;
    if (i >= (size_t)(NN + NE) * 32) return;
    int c4 = (int)(i & 31) * 4;
    int bn = (i < (size_t)NN * 32) ? 2 : 3;
    const float* ab = g_bnab + bn * 2 * D;
    float4 v = out[i];
    v.x = fmaf(v.x, ab[c4 + 0], ab[128 + c4 + 0]);
    v.y = fmaf(v.y, ab[c4 + 1], ab[128 + c4 + 1]);
    v.z = fmaf(v.z, ab[c4 + 2], ab[128 + c4 + 2]);
    v.w = fmaf(v.w, ab[c4 + 3], ab[128 + c4 + 3]);
    out[i] = v;
}

// ---------------- host ----------------
extern "C" void kernel_launch(void* const* d_in, const int* in_sizes, int n_in,
                              void* d_out, int out_size)
{
    (void)in_sizes; (void)n_in; (void)out_size;
    const float* h_in  = (const float*)d_in[0];
    const float* e_in  = (const float*)d_in[1];
    const float* Wq    = (const float*)d_in[2];
    const float* Wk    = (const float*)d_in[3];
    const float* Wv    = (const float*)d_in[4];
    const float* We    = (const float*)d_in[5];
    const float* Ohw   = (const float*)d_in[6];
    const float* Ohb   = (const float*)d_in[7];
    const float* Oew   = (const float*)d_in[8];
    const float* Oeb   = (const float*)d_in[9];
    const float* bn1hg = (const float*)d_in[10];
    const float* bn1hb = (const float*)d_in[11];
    const float* bn1eg = (const float*)d_in[12];
    const float* bn1eb = (const float*)d_in[13];
    const float* fhw1  = (const float*)d_in[14];
    const float* fhb1  = (const float*)d_in[15];
    const float* fhw2  = (const float*)d_in[16];
    const float* fhb2  = (const float*)d_in[17];
    const float* few1  = (const float*)d_in[18];
    const float* feb1  = (const float*)d_in[19];
    const float* few2  = (const float*)d_in[20];
    const float* feb2  = (const float*)d_in[21];
    const float* bn2hg = (const float*)d_in[22];
    const float* bn2hb = (const float*)d_in[23];
    const float* bn2eg = (const float*)d_in[24];
    const float* bn2eb = (const float*)d_in[25];
    const int*   src   = (const int*)d_in[26];
    const int*   dst   = (const int*)d_in[27];

    float* out  = (float*)d_out;
    float* outh = out;
    float* oute = out + (size_t)NN * D;

    float *pQ, *pK, *pV, *pwV, *pz, *ph2, *pe2, *pstats, *pbnab;
    __nv_bfloat16* pimg;
    cudaGetSymbolAddress((void**)&pQ,    g_Q);
    cudaGetSymbolAddress((void**)&pK,    g_Kb);
    cudaGetSymbolAddress((void**)&pV,    g_V);
    cudaGetSymbolAddress((void**)&pwV,   g_wV);
    cudaGetSymbolAddress((void**)&pz,    g_z);
    cudaGetSymbolAddress((void**)&ph2,   g_h2);
    cudaGetSymbolAddress((void**)&pe2,   g_e2);
    cudaGetSymbolAddress((void**)&pstats, g_stats);
    cudaGetSymbolAddress((void**)&pbnab,  g_bnab);
    cudaGetSymbolAddress((void**)&pimg,   g_wimg);

    const size_t oWe = 0, oWq = 32768, oWk = 65536, oWv = 98304;
    const size_t oOh = 131072, oOe = 163840;
    const size_t oF1h = 196608, oF1e = 262144, oF2h = 327680, oF2e = 393216;

    auto kBh = mm_k<1, 1, 1, 1>;

    const int SMEM_64 = 2 * 64 * 136 * 2;
    const int SMEM_E  = 4 * 64 * 136 * 2;
    const int SMEM_F  = 2 * 64 * 264 * 2;
    cudaFuncSetAttribute(kBh,   cudaFuncAttributeMaxDynamicSharedMemorySize, SMEM_64);
    cudaFuncSetAttribute(qkv_k, cudaFuncAttributeMaxDynamicSharedMemorySize, SMEM_64);
    cudaFuncSetAttribute(epj_k, cudaFuncAttributeMaxDynamicSharedMemorySize, SMEM_E);
    cudaFuncSetAttribute(ffn_k, cudaFuncAttributeMaxDynamicSharedMemorySize, SMEM_F);

    const int gN64 = (NN + 63) / 64;
    const int gE64 = (NE + 63) / 64;

    cudaMemsetAsync(pwV,    0, sizeof(float) * NN * D);
    cudaMemsetAsync(pz,     0, sizeof(float) * NN * 8);
    cudaMemsetAsync(pstats, 0, sizeof(float) * 4 * 2 * D);

    PrepArgs pa;
    pa.src[0] = We;   pa.src[1] = Wq;   pa.src[2] = Wk;   pa.src[3] = Wv;
    pa.src[4] = Ohw;  pa.src[5] = Oew;
    pa.src[6] = fhw1; pa.src[7] = few1; pa.src[8] = fhw2; pa.src[9] = few2;
    prep_all<<<(229376 + 255) / 256, 256>>>(pa, pimg);

    qkv_k<<<dim3(1, gN64), 256, SMEM_64>>>(h_in, pimg + oWq, pimg + oWk, pimg + oWv, pQ, pK, pV, NN);

    epj_k<<<gE64, 256, SMEM_E>>>(e_in, pimg + oWe, pimg + oOe, Oeb, src, dst,
                                 pstats + 1 * 2 * D, pe2, NE);

    kBh<<<dim3(1, gN64), 256, SMEM_64>>>(pwV, pimg + oOh, Ohb, h_in, nullptr, pz,
                                         pstats + 0 * 2 * D, ph2, NN);

    finalize_bn2<<<2, D>>>(0, bn1hg, bn1hb, 1.f / NN, 1, bn1eg, bn1eb, 1.f / NE);

    ffn_k<<<gN64 + gE64, 256, SMEM_F>>>(ph2, pe2,
                                        pimg + oF1h, pimg + oF1e, fhb1, feb1,
                                        pimg + oF2h, pimg + oF2e, fhb2, feb2,
                                        pbnab + 0 * 2 * D, pbnab + 1 * 2 * D,
                                        pstats + 2 * 2 * D, pstats + 3 * 2 * D,
                                        outh, oute, gN64);

    finalize_bn2<<<2, D>>>(2, bn2hg, bn2hb, 1.f / NN, 3, bn2eg, bn2eb, 1.f / NE);

    out_norm<<<(int)(((size_t)(NN + NE) * 32 + 255) / 256), 256>>>((float4*)out);
}